// round 12
// baseline (speedup 1.0000x reference)
#include <cuda_runtime.h>
#include <cuda_fp16.h>
#include <cstdint>

#define N_NODES 50000
#define N_PAD   50048      // multiple of 128 for MMA tiles
#define N_EDGES 800000
#define IN_CH 256
#define HID 256
#define OUT_CH 128
#define N_GRAPHS 64

// ---------------- scratch (device globals; no cudaMalloc allowed) ----------
__device__ float g_dinv[N_NODES];
__device__ int   g_degi[N_NODES];
__device__ int   g_offs[N_NODES];
__device__ int   g_cursor[N_NODES];
__device__ int   g_ssrc[N_EDGES];
__device__ float g_swgt[N_EDGES];
__device__ __half g_h1[(size_t)N_PAD * HID];
__device__ __half g_h2[(size_t)N_PAD * OUT_CH];
__device__ int   g_counts[N_GRAPHS];
__device__ int   g_src[N_EDGES];
__device__ int   g_dst[N_EDGES];
__device__ int   g_batch[N_NODES];
__device__ int   g_oddcnt[2];             // [0]=edge_index, [1]=batch
// fp16 operands. Pad rows (>= N_NODES) of g_a2 stay zero: zero-initialized
// device globals, never written.
__device__ __half g_a2[(size_t)N_PAD * HID];
__device__ __half g_w1t[HID * IN_CH];     // [n][k] = W1[k][n]
__device__ __half g_w2t[OUT_CH * HID];

// ---------------- helpers ---------------------------------------------------
__device__ __forceinline__ void red_add_v4(float* addr, float4 v) {
    asm volatile("red.global.add.v4.f32 [%0], {%1,%2,%3,%4};"
                 :: "l"(addr), "f"(v.x), "f"(v.y), "f"(v.z), "f"(v.w) : "memory");
}
__device__ __forceinline__ void mma_f16(float* c, uint32_t a0, uint32_t a1,
                                        uint32_t a2, uint32_t a3,
                                        uint32_t b0, uint32_t b1) {
    asm volatile("mma.sync.aligned.m16n8k16.row.col.f32.f16.f16.f32 "
                 "{%0,%1,%2,%3}, {%4,%5,%6,%7}, {%8,%9}, {%0,%1,%2,%3};"
                 : "+f"(c[0]), "+f"(c[1]), "+f"(c[2]), "+f"(c[3])
                 : "r"(a0), "r"(a1), "r"(a2), "r"(a3), "r"(b0), "r"(b1));
}
__device__ __forceinline__ uint32_t pack_h2(float a, float b) {
    __half2 h = __floats2half2_rn(a, b);
    return *reinterpret_cast<uint32_t*>(&h);
}

// ------- dtype detection + zero-init of degi/counts/out (one kernel) --------
__global__ void detect_zero_kernel(const int* __restrict__ ei32,
                                   const int* __restrict__ bat32,
                                   int* __restrict__ cnt,
                                   int* __restrict__ degi,
                                   int* __restrict__ counts,
                                   float* __restrict__ outz) {
    int i = blockIdx.x * blockDim.x + threadIdx.x;
    if (i < N_NODES) degi[i] = 0;
    if (i < N_GRAPHS) counts[i] = 0;
    if (i < N_GRAPHS * OUT_CH) outz[i] = 0.0f;
    int local = 0, which = -1;
    if (i < 800000)       { which = 0; local = (ei32[2 * i + 1] != 0); }
    else if (i < 825000)  { which = 1; local = (bat32[2 * (i - 800000) + 1] != 0); }
    unsigned m = __ballot_sync(0xFFFFFFFFu, local);
    if ((threadIdx.x & 31) == 0 && m && which >= 0) atomicAdd(&cnt[which], __popc(m));
}
// fused: edge conversion + degree histogram
__global__ void ei_hist_kernel(const void* __restrict__ ei, int* __restrict__ src,
                               int* __restrict__ dst, const int* __restrict__ cnt,
                               int* __restrict__ degi) {
    int e = blockIdx.x * blockDim.x + threadIdx.x;
    if (e >= N_EDGES) return;
    int s, d;
    if (cnt[0] < 100) { const long long* p = (const long long*)ei; s = (int)p[e]; d = (int)p[N_EDGES + e]; }
    else              { const int* p = (const int*)ei;             s = p[e];      d = p[N_EDGES + e]; }
    s = min(max(s, 0), N_NODES - 1);
    d = min(max(d, 0), N_NODES - 1);
    src[e] = s;
    dst[e] = d;
    atomicAdd(&degi[d], 1);
}
// fused: batch conversion + dinv + per-graph node counts
__global__ void bat_dinv_kernel(const void* __restrict__ bat, int* __restrict__ batch,
                                const int* __restrict__ cnt,
                                const int* __restrict__ degi, float* __restrict__ dinv,
                                int* __restrict__ counts) {
    int i = blockIdx.x * blockDim.x + threadIdx.x;
    if (i >= N_NODES) return;
    int g;
    if (cnt[1] < 100) g = (int)((const long long*)bat)[i];
    else              g = ((const int*)bat)[i];
    g = min(max(g, 0), N_GRAPHS - 1);
    batch[i] = g;
    dinv[i] = rsqrtf((float)degi[i] + 1.0f);
    atomicAdd(&counts[g], 1);
}

// ---------------- weight transpose + fp16 convert (both weights) -------------
__global__ void conv_w_kernel(const float* __restrict__ W1, const float* __restrict__ W2,
                              __half* __restrict__ w1t, __half* __restrict__ w2t) {
    int i = blockIdx.x * blockDim.x + threadIdx.x;
    if (i < HID * IN_CH) {
        int n = i / IN_CH, k = i % IN_CH;
        w1t[(size_t)n * IN_CH + k] = __float2half_rn(W1[(size_t)k * HID + n]);
    } else {
        int j = i - HID * IN_CH;
        if (j < OUT_CH * HID) {
            int n = j / HID, k = j % HID;
            w2t[(size_t)n * HID + k] = __float2half_rn(W2[(size_t)k * OUT_CH + n]);
        }
    }
}

// ---------------- single-block CSR scan (exclusive) ---------------------------
// 1024 threads, 50 coalesced 1024-wide tile scans with a running offset.
__global__ __launch_bounds__(1024) void scan_block_kernel(
    const int* __restrict__ degi, int* __restrict__ offs, int* __restrict__ cursor) {
    __shared__ int wsum[32];
    const int tid  = threadIdx.x;
    const int lane = tid & 31;
    const int wid  = tid >> 5;
    int running = 0;
    const int NTILES = (N_NODES + 1023) / 1024;   // 49
    for (int t = 0; t < NTILES; t++) {
        int idx = t * 1024 + tid;
        int v = (idx < N_NODES) ? degi[idx] : 0;
        int inc = v;
        #pragma unroll
        for (int d = 1; d < 32; d <<= 1) {
            int u = __shfl_up_sync(0xFFFFFFFFu, inc, d);
            if (lane >= d) inc += u;
        }
        if (lane == 31) wsum[wid] = inc;
        __syncthreads();
        if (wid == 0) {
            int w = wsum[lane];
            #pragma unroll
            for (int d = 1; d < 32; d <<= 1) {
                int u = __shfl_up_sync(0xFFFFFFFFu, w, d);
                if (lane >= d) w += u;
            }
            wsum[lane] = w;
        }
        __syncthreads();
        int excl = running + ((wid > 0) ? wsum[wid - 1] : 0) + inc - v;
        if (idx < N_NODES) { offs[idx] = excl; cursor[idx] = excl; }
        running += wsum[31];
        __syncthreads();
    }
}
// build sorted src + precomputed edge weight dinv[s]*dinv[d]
__global__ void scatter_build_kernel(const int* __restrict__ src, const int* __restrict__ dst,
                                     int* __restrict__ cursor, int* __restrict__ ssrc,
                                     float* __restrict__ swgt,
                                     const float* __restrict__ dinv) {
    int e = blockIdx.x * blockDim.x + threadIdx.x;
    if (e >= N_EDGES) return;
    int s = src[e], d = dst[e];
    int pos = atomicAdd(&cursor[d], 1);
    ssrc[pos] = s;
    swgt[pos] = dinv[s] * dinv[d];
}

// ---------------- HMMA GEMM: C[Mpad,NT] = A[Mpad,256] @ Wt[NT,256]^T --------
#define PADK 40
template <int NT, bool AFP32>
__global__ __launch_bounds__(256) void mma_gemm_kernel(
    const void* __restrict__ A_,
    const __half* __restrict__ B,
    __half* __restrict__ C)
{
    constexpr int K = 256;
    __shared__ __align__(16) __half sA[128 * PADK];
    __shared__ __align__(16) __half sB[128 * PADK];

    const int tid  = threadIdx.x;
    const int lane = tid & 31;
    const int wid  = tid >> 5;
    const int wm   = wid & 3;
    const int wn   = wid >> 2;
    const int bm   = blockIdx.y * 128;
    const int bn   = blockIdx.x * 128;

    const int r0l = tid >> 2, i0l = (tid & 3) * 8;
    const int r1l = r0l + 64;

    float acc[2][8][4];
    #pragma unroll
    for (int mt = 0; mt < 2; mt++)
        #pragma unroll
        for (int nt = 0; nt < 8; nt++)
            #pragma unroll
            for (int j = 0; j < 4; j++) acc[mt][nt][j] = 0.0f;

    const int qr = lane >> 2;
    const int qc = (lane & 3) * 2;

    float4 pAf[2][2];
    uint4  pA[2];
    uint4  pB[2];

    auto prefetch = [&](int kc) {
        if constexpr (AFP32) {
            const float* A = (const float*)A_;
            #pragma unroll
            for (int it = 0; it < 2; it++) {
                int r = (it == 0) ? r0l : r1l;
                if (bm + r < N_NODES) {
                    size_t gi = (size_t)(bm + r) * K + kc + i0l;
                    pAf[it][0] = *(const float4*)(A + gi);
                    pAf[it][1] = *(const float4*)(A + gi + 4);
                } else {
                    pAf[it][0] = make_float4(0.f, 0.f, 0.f, 0.f);
                    pAf[it][1] = make_float4(0.f, 0.f, 0.f, 0.f);
                }
            }
        } else {
            const __half* A = (const __half*)A_;
            #pragma unroll
            for (int it = 0; it < 2; it++) {
                int r = (it == 0) ? r0l : r1l;
                size_t gi = (size_t)(bm + r) * K + kc + i0l;
                pA[it] = *(const uint4*)(A + gi);
            }
        }
        #pragma unroll
        for (int it = 0; it < 2; it++) {
            int r = (it == 0) ? r0l : r1l;
            size_t gi = (size_t)(bn + r) * K + kc + i0l;
            pB[it] = *(const uint4*)(B + gi);
        }
    };

    auto stage = [&]() {
        if constexpr (AFP32) {
            #pragma unroll
            for (int it = 0; it < 2; it++) {
                int r = (it == 0) ? r0l : r1l;
                uint4 v;
                v.x = pack_h2(pAf[it][0].x, pAf[it][0].y);
                v.y = pack_h2(pAf[it][0].z, pAf[it][0].w);
                v.z = pack_h2(pAf[it][1].x, pAf[it][1].y);
                v.w = pack_h2(pAf[it][1].z, pAf[it][1].w);
                *(uint4*)&sA[r * PADK + i0l] = v;
            }
        } else {
            #pragma unroll
            for (int it = 0; it < 2; it++) {
                int r = (it == 0) ? r0l : r1l;
                *(uint4*)&sA[r * PADK + i0l] = pA[it];
            }
        }
        #pragma unroll
        for (int it = 0; it < 2; it++) {
            int r = (it == 0) ? r0l : r1l;
            *(uint4*)&sB[r * PADK + i0l] = pB[it];
        }
    };

    prefetch(0);
    for (int kc = 0; kc < K; kc += 32) {
        stage();
        __syncthreads();
        if (kc + 32 < K) prefetch(kc + 32);   // LDGs overlap with MMAs below

        #pragma unroll
        for (int ks = 0; ks < 2; ks++) {
            const int kb = ks * 16;
            uint32_t ah[2][4];
            #pragma unroll
            for (int mt = 0; mt < 2; mt++) {
                int rr = wm * 32 + mt * 16 + qr;
                #pragma unroll
                for (int h = 0; h < 2; h++) {
                    int r = rr + h * 8;
                    ah[mt][h]     = *(const uint32_t*)&sA[r * PADK + kb + qc];
                    ah[mt][h + 2] = *(const uint32_t*)&sA[r * PADK + kb + qc + 8];
                }
            }
            #pragma unroll
            for (int nt = 0; nt < 8; nt++) {
                int n = wn * 64 + nt * 8 + qr;
                uint32_t b0 = *(const uint32_t*)&sB[n * PADK + kb + qc];
                uint32_t b1 = *(const uint32_t*)&sB[n * PADK + kb + qc + 8];
                #pragma unroll
                for (int mt = 0; mt < 2; mt++)
                    mma_f16(acc[mt][nt], ah[mt][0], ah[mt][1], ah[mt][2], ah[mt][3],
                            b0, b1);
            }
        }
        __syncthreads();
    }

    #pragma unroll
    for (int mt = 0; mt < 2; mt++) {
        #pragma unroll
        for (int nt = 0; nt < 8; nt++) {
            int r0 = bm + wm * 32 + mt * 16 + qr;
            int c0 = bn + wn * 64 + nt * 8 + qc;
            *(uint32_t*)(C + (size_t)r0 * NT + c0) = pack_h2(acc[mt][nt][0], acc[mt][nt][1]);
            *(uint32_t*)(C + (size_t)(r0 + 8) * NT + c0) = pack_h2(acc[mt][nt][2], acc[mt][nt][3]);
        }
    }
}

// ---------------- CSR gather aggregation (fp16 features) ---------------------
// Warp per node; per 32-edge chunk two coalesced LDGs + shfl broadcast.
// MODE 0 (layer 1, F=256): out = fp16(ELU(agg + h/deg + b)) -> a2
// MODE 1 (layer 2, F=128): red-add (agg + h/deg + b)/count[g] directly into out
template <int F, int MODE>
__global__ __launch_bounds__(128) void gather_kernel(
    const int* __restrict__ offs, const int* __restrict__ degi,
    const int* __restrict__ ssrc, const float* __restrict__ swgt,
    const float* __restrict__ dinv,
    const __half* __restrict__ h, const float* __restrict__ bias,
    __half* __restrict__ oh,
    const int* __restrict__ batch, float* __restrict__ out,
    const int* __restrict__ counts)
{
    constexpr int HPL = F / 32;                   // halves per lane: 8 or 4
    int node = blockIdx.x * 4 + (threadIdx.x >> 5);
    int lane = threadIdx.x & 31;
    if (node >= N_NODES) return;

    int start = offs[node];
    int dg    = degi[node];
    float dn  = dinv[node];

    float acc[HPL];
    #pragma unroll
    for (int v = 0; v < HPL; v++) acc[v] = 0.0f;

    auto accum = [&](int s, float w) {
        if constexpr (HPL == 8) {
            uint4 v = __ldg((const uint4*)(h + (size_t)s * F) + lane);
            const __half2* hp = (const __half2*)&v;
            #pragma unroll
            for (int i = 0; i < 4; i++) {
                float2 f = __half22float2(hp[i]);
                acc[2 * i]     += w * f.x;
                acc[2 * i + 1] += w * f.y;
            }
        } else {
            uint2 v = __ldg((const uint2*)(h + (size_t)s * F) + lane);
            const __half2* hp = (const __half2*)&v;
            #pragma unroll
            for (int i = 0; i < 2; i++) {
                float2 f = __half22float2(hp[i]);
                acc[2 * i]     += w * f.x;
                acc[2 * i + 1] += w * f.y;
            }
        }
    };

    for (int base = 0; base < dg; base += 32) {
        int nch = min(32, dg - base);
        int   s_l = 0;
        float w_l = 0.0f;
        if (lane < nch) {
            s_l = __ldg(&ssrc[start + base + lane]);     // coalesced
            w_l = __ldg(&swgt[start + base + lane]);     // coalesced (precomputed)
        }
        #pragma unroll 4
        for (int j = 0; j < nch; j++) {
            int   s = __shfl_sync(0xFFFFFFFFu, s_l, j);
            float w = __shfl_sync(0xFFFFFFFFu, w_l, j);
            accum(s, w);                                 // independent h-row loads
        }
    }

    float sl = dn * dn;      // 1/deg (self-loop weight)
    int col = lane * HPL;
    float selfv[HPL];
    if constexpr (HPL == 8) {
        uint4 v = __ldg((const uint4*)(h + (size_t)node * F) + lane);
        const __half2* hp = (const __half2*)&v;
        #pragma unroll
        for (int i = 0; i < 4; i++) {
            float2 f = __half22float2(hp[i]);
            selfv[2 * i] = f.x; selfv[2 * i + 1] = f.y;
        }
    } else {
        uint2 v = __ldg((const uint2*)(h + (size_t)node * F) + lane);
        const __half2* hp = (const __half2*)&v;
        #pragma unroll
        for (int i = 0; i < 2; i++) {
            float2 f = __half22float2(hp[i]);
            selfv[2 * i] = f.x; selfv[2 * i + 1] = f.y;
        }
    }

    if constexpr (MODE == 0) {
        uint32_t outw[HPL / 2];
        #pragma unroll
        for (int i = 0; i < HPL; i += 2) {
            float r0 = acc[i]     + selfv[i]     * sl + bias[col + i];
            float r1 = acc[i + 1] + selfv[i + 1] * sl + bias[col + i + 1];
            r0 = r0 > 0.f ? r0 : expm1f(r0);
            r1 = r1 > 0.f ? r1 : expm1f(r1);
            outw[i / 2] = pack_h2(r0, r1);
        }
        *(uint4*)(oh + (size_t)node * F + col) =
            make_uint4(outw[0], outw[1], outw[2], outw[3]);
    } else {
        int g = batch[node];
        float ic = 1.0f / fmaxf((float)counts[g], 1.0f);
        float4 bv = *(const float4*)(bias + col);
        float4 r = make_float4((acc[0] + selfv[0] * sl + bv.x) * ic,
                               (acc[1] + selfv[1] * sl + bv.y) * ic,
                               (acc[2] + selfv[2] * sl + bv.z) * ic,
                               (acc[3] + selfv[3] * sl + bv.w) * ic);
        red_add_v4(out + g * F + col, r);
    }
}

__global__ void zero_out_kernel(float* out, int n) {
    int i = blockIdx.x * blockDim.x + threadIdx.x;
    if (i < n) out[i] = 0.0f;
}

// ---------------- launch -----------------------------------------------------
extern "C" void kernel_launch(void* const* d_in, const int* in_sizes, int n_in,
                              void* d_out, int out_size)
{
    const float* x   = nullptr;
    const float* W1  = nullptr;
    const float* b1  = nullptr;
    const float* W2  = nullptr;
    const float* b2  = nullptr;
    const void*  ei  = nullptr;
    const void*  bat = nullptr;

    for (int i = 0; i < n_in; i++) {
        switch (in_sizes[i]) {
            case 12800000: x   = (const float*)d_in[i]; break;
            case 65536:    W1  = (const float*)d_in[i]; break;
            case 256:      b1  = (const float*)d_in[i]; break;
            case 32768:    W2  = (const float*)d_in[i]; break;
            case 128:      b2  = (const float*)d_in[i]; break;
            case 1600000:  ei  = d_in[i];               break;
            case 50000:    bat = d_in[i];               break;
            default: break;
        }
    }
    float* out = (float*)d_out;

    if (!x || !W1 || !b1 || !W2 || !b2 || !ei || !bat) {
        zero_out_kernel<<<(out_size + 255) / 256, 256>>>(out, out_size);
        return;
    }

    void* p;
    cudaGetSymbolAddress(&p, g_dinv);    float* dinv   = (float*)p;
    cudaGetSymbolAddress(&p, g_degi);    int*   degi   = (int*)p;
    cudaGetSymbolAddress(&p, g_offs);    int*   offs   = (int*)p;
    cudaGetSymbolAddress(&p, g_cursor);  int*   cursor = (int*)p;
    cudaGetSymbolAddress(&p, g_ssrc);    int*   ssrc   = (int*)p;
    cudaGetSymbolAddress(&p, g_swgt);    float* swgt   = (float*)p;
    cudaGetSymbolAddress(&p, g_h1);      __half* h1    = (__half*)p;
    cudaGetSymbolAddress(&p, g_h2);      __half* h2    = (__half*)p;
    cudaGetSymbolAddress(&p, g_counts);  int*   counts = (int*)p;
    cudaGetSymbolAddress(&p, g_src);     int*   src    = (int*)p;
    cudaGetSymbolAddress(&p, g_dst);     int*   dst    = (int*)p;
    cudaGetSymbolAddress(&p, g_batch);   int*   batch  = (int*)p;
    cudaGetSymbolAddress(&p, g_oddcnt);  int*   oddc   = (int*)p;
    cudaGetSymbolAddress(&p, g_a2);      __half* a2    = (__half*)p;
    cudaGetSymbolAddress(&p, g_w1t);     __half* w1t   = (__half*)p;
    cudaGetSymbolAddress(&p, g_w2t);     __half* w2t   = (__half*)p;

    // static host-side resources (streams/events are NOT device memory)
    static cudaStream_t s2 = nullptr;
    static cudaEvent_t evFork = nullptr, evJoin = nullptr;
    if (!s2) {
        cudaStreamCreateWithFlags(&s2, cudaStreamNonBlocking);
        cudaEventCreateWithFlags(&evFork, cudaEventDisableTiming);
        cudaEventCreateWithFlags(&evJoin, cudaEventDisableTiming);
    }

    // ---- fork: weights + GEMM1 on s2, independent of the CSR chain ----
    cudaEventRecord(evFork, 0);
    cudaStreamWaitEvent(s2, evFork, 0);

    conv_w_kernel<<<(HID * IN_CH + OUT_CH * HID + 255) / 256, 256, 0, s2>>>(
        W1, W2, w1t, w2t);
    mma_gemm_kernel<HID, true><<<dim3(HID / 128, N_PAD / 128), 256, 0, s2>>>(
        x, w1t, h1);
    cudaEventRecord(evJoin, s2);

    // ---- main stream: CSR build chain ----
    cudaMemsetAsync(oddc, 0, 2 * sizeof(int));
    detect_zero_kernel<<<(825000 + 255) / 256, 256>>>(
        (const int*)ei, (const int*)bat, oddc, degi, counts, out);
    ei_hist_kernel<<<(N_EDGES + 255) / 256, 256>>>(ei, src, dst, oddc, degi);
    bat_dinv_kernel<<<(N_NODES + 255) / 256, 256>>>(bat, batch, oddc, degi, dinv, counts);
    scan_block_kernel<<<1, 1024>>>(degi, offs, cursor);
    scatter_build_kernel<<<(N_EDGES + 255) / 256, 256>>>(src, dst, cursor, ssrc, swgt, dinv);

    // ---- join: gather1 needs both h1 (s2) and CSR (main) ----
    cudaStreamWaitEvent(0, evJoin, 0);

    gather_kernel<HID, 0><<<(N_NODES + 3) / 4, 128>>>(
        offs, degi, ssrc, swgt, dinv, h1, b1, a2, nullptr, nullptr, nullptr);

    mma_gemm_kernel<OUT_CH, false><<<dim3(OUT_CH / 128, N_PAD / 128), 256>>>(a2, w2t, h2);

    // layer-2 gather + bias + mean-pool directly into d_out
    gather_kernel<OUT_CH, 1><<<(N_NODES + 3) / 4, 128>>>(
        offs, degi, ssrc, swgt, dinv, h2, b2, nullptr, batch, out, counts);
}

// round 13
// speedup vs baseline: 1.0518x; 1.0518x over previous
#include <cuda_runtime.h>
#include <cuda_fp16.h>
#include <cstdint>

#define N_NODES 50000
#define N_PAD   50048      // multiple of 128 for MMA tiles
#define N_EDGES 800000
#define IN_CH 256
#define HID 256
#define OUT_CH 128
#define N_GRAPHS 64
#define SCAN_BLK 512
#define SCAN_NB  ((N_NODES + SCAN_BLK - 1) / SCAN_BLK)   // 98

// ---------------- scratch (device globals; no cudaMalloc allowed) ----------
__device__ float g_dinv[N_NODES];
__device__ int   g_degi[N_NODES];
__device__ int   g_offs[N_NODES];
__device__ int   g_cursor[N_NODES];
__device__ int   g_partials[SCAN_NB];
__device__ int   g_ssrc[N_EDGES];
__device__ float g_swgt[N_EDGES];
__device__ __half g_h1[(size_t)N_PAD * HID];
__device__ __half g_h2[(size_t)N_PAD * OUT_CH];
__device__ int   g_counts[N_GRAPHS];
__device__ int   g_src[N_EDGES];
__device__ int   g_dst[N_EDGES];
__device__ int   g_batch[N_NODES];
__device__ int   g_oddcnt[2];             // [0]=edge_index, [1]=batch
// fp16 operands. Pad rows (>= N_NODES) of g_a2 stay zero: zero-initialized
// device globals, never written.
__device__ __half g_a2[(size_t)N_PAD * HID];
__device__ __half g_w1t[HID * IN_CH];     // [n][k] = W1[k][n]
__device__ __half g_w2t[OUT_CH * HID];

// ---------------- helpers ---------------------------------------------------
__device__ __forceinline__ void red_add_v4(float* addr, float4 v) {
    asm volatile("red.global.add.v4.f32 [%0], {%1,%2,%3,%4};"
                 :: "l"(addr), "f"(v.x), "f"(v.y), "f"(v.z), "f"(v.w) : "memory");
}
__device__ __forceinline__ void mma_f16(float* c, uint32_t a0, uint32_t a1,
                                        uint32_t a2, uint32_t a3,
                                        uint32_t b0, uint32_t b1) {
    asm volatile("mma.sync.aligned.m16n8k16.row.col.f32.f16.f16.f32 "
                 "{%0,%1,%2,%3}, {%4,%5,%6,%7}, {%8,%9}, {%0,%1,%2,%3};"
                 : "+f"(c[0]), "+f"(c[1]), "+f"(c[2]), "+f"(c[3])
                 : "r"(a0), "r"(a1), "r"(a2), "r"(a3), "r"(b0), "r"(b1));
}
__device__ __forceinline__ uint32_t pack_h2(float a, float b) {
    __half2 h = __floats2half2_rn(a, b);
    return *reinterpret_cast<uint32_t*>(&h);
}

// ---------------- dtype detection (both buffers, one kernel) -----------------
__global__ void detect_kernel(const int* __restrict__ ei32, const int* __restrict__ bat32,
                              int* __restrict__ cnt) {
    int i = blockIdx.x * blockDim.x + threadIdx.x;
    int local = 0, which = -1;
    if (i < 800000)       { which = 0; local = (ei32[2 * i + 1] != 0); }
    else if (i < 825000)  { which = 1; local = (bat32[2 * (i - 800000) + 1] != 0); }
    unsigned m = __ballot_sync(0xFFFFFFFFu, local);
    if ((threadIdx.x & 31) == 0 && m && which >= 0) atomicAdd(&cnt[which], __popc(m));
}
// fused: edge conversion + degree histogram
__global__ void ei_hist_kernel(const void* __restrict__ ei, int* __restrict__ src,
                               int* __restrict__ dst, const int* __restrict__ cnt,
                               int* __restrict__ degi) {
    int e = blockIdx.x * blockDim.x + threadIdx.x;
    if (e >= N_EDGES) return;
    int s, d;
    if (cnt[0] < 100) { const long long* p = (const long long*)ei; s = (int)p[e]; d = (int)p[N_EDGES + e]; }
    else              { const int* p = (const int*)ei;             s = p[e];      d = p[N_EDGES + e]; }
    s = min(max(s, 0), N_NODES - 1);
    d = min(max(d, 0), N_NODES - 1);
    src[e] = s;
    dst[e] = d;
    atomicAdd(&degi[d], 1);
}
// fused: batch conversion + dinv + per-graph node counts
__global__ void bat_dinv_kernel(const void* __restrict__ bat, int* __restrict__ batch,
                                const int* __restrict__ cnt,
                                const int* __restrict__ degi, float* __restrict__ dinv,
                                int* __restrict__ counts) {
    int i = blockIdx.x * blockDim.x + threadIdx.x;
    if (i >= N_NODES) return;
    int g;
    if (cnt[1] < 100) g = (int)((const long long*)bat)[i];
    else              g = ((const int*)bat)[i];
    g = min(max(g, 0), N_GRAPHS - 1);
    batch[i] = g;
    dinv[i] = rsqrtf((float)degi[i] + 1.0f);
    atomicAdd(&counts[g], 1);
}

// ---------------- weight transpose + fp16 convert (both weights) -------------
__global__ void conv_w_kernel(const float* __restrict__ W1, const float* __restrict__ W2,
                              __half* __restrict__ w1t, __half* __restrict__ w2t) {
    int i = blockIdx.x * blockDim.x + threadIdx.x;
    if (i < HID * IN_CH) {
        int n = i / IN_CH, k = i % IN_CH;
        w1t[(size_t)n * IN_CH + k] = __float2half_rn(W1[(size_t)k * HID + n]);
    } else {
        int j = i - HID * IN_CH;
        if (j < OUT_CH * HID) {
            int n = j / HID, k = j % HID;
            w2t[(size_t)n * HID + k] = __float2half_rn(W2[(size_t)k * OUT_CH + n]);
        }
    }
}

// ---------------- CSR scan (multi-block, proven) ------------------------------
__global__ __launch_bounds__(SCAN_BLK) void scan1_kernel(
    const int* __restrict__ degi, int* __restrict__ offs, int* __restrict__ partials) {
    __shared__ int sm[SCAN_BLK];
    int i = blockIdx.x * SCAN_BLK + threadIdx.x;
    int v = (i < N_NODES) ? degi[i] : 0;
    sm[threadIdx.x] = v;
    __syncthreads();
    for (int d = 1; d < SCAN_BLK; d <<= 1) {
        int t = (threadIdx.x >= d) ? sm[threadIdx.x - d] : 0;
        __syncthreads();
        sm[threadIdx.x] += t;
        __syncthreads();
    }
    if (i < N_NODES) offs[i] = sm[threadIdx.x] - v;       // exclusive
    if (threadIdx.x == SCAN_BLK - 1) partials[blockIdx.x] = sm[SCAN_BLK - 1];
}
// single-warp shfl scan over SCAN_NB partials (exclusive)
__global__ void scan2_kernel(int* __restrict__ partials) {
    int lane = threadIdx.x;
    int run = 0;
    for (int b = 0; b < SCAN_NB; b += 32) {
        int idx = b + lane;
        int orig = (idx < SCAN_NB) ? partials[idx] : 0;
        int v = orig;
        #pragma unroll
        for (int d = 1; d < 32; d <<= 1) {
            int t = __shfl_up_sync(0xFFFFFFFFu, v, d);
            if (lane >= d) v += t;
        }
        if (idx < SCAN_NB) partials[idx] = run + v - orig;   // exclusive
        run += __shfl_sync(0xFFFFFFFFu, v, 31);
    }
}
__global__ void scan3_kernel(int* __restrict__ offs, int* __restrict__ cursor,
                             const int* __restrict__ partials) {
    int i = blockIdx.x * blockDim.x + threadIdx.x;
    if (i < N_NODES) {
        int o = offs[i] + partials[i / SCAN_BLK];
        offs[i] = o;
        cursor[i] = o;
    }
}
// build sorted src + precomputed edge weight dinv[s]*dinv[d]
__global__ void scatter_build_kernel(const int* __restrict__ src, const int* __restrict__ dst,
                                     int* __restrict__ cursor, int* __restrict__ ssrc,
                                     float* __restrict__ swgt,
                                     const float* __restrict__ dinv) {
    int e = blockIdx.x * blockDim.x + threadIdx.x;
    if (e >= N_EDGES) return;
    int s = src[e], d = dst[e];
    int pos = atomicAdd(&cursor[d], 1);
    ssrc[pos] = s;
    swgt[pos] = dinv[s] * dinv[d];
}

// ---------------- HMMA GEMM: C[Mpad,NT] = A[Mpad,256] @ Wt[NT,256]^T --------
#define PADK 40
template <int NT, bool AFP32>
__global__ __launch_bounds__(256) void mma_gemm_kernel(
    const void* __restrict__ A_,
    const __half* __restrict__ B,
    __half* __restrict__ C)
{
    constexpr int K = 256;
    __shared__ __align__(16) __half sA[128 * PADK];
    __shared__ __align__(16) __half sB[128 * PADK];

    const int tid  = threadIdx.x;
    const int lane = tid & 31;
    const int wid  = tid >> 5;
    const int wm   = wid & 3;
    const int wn   = wid >> 2;
    const int bm   = blockIdx.y * 128;
    const int bn   = blockIdx.x * 128;

    const int r0l = tid >> 2, i0l = (tid & 3) * 8;
    const int r1l = r0l + 64;

    float acc[2][8][4];
    #pragma unroll
    for (int mt = 0; mt < 2; mt++)
        #pragma unroll
        for (int nt = 0; nt < 8; nt++)
            #pragma unroll
            for (int j = 0; j < 4; j++) acc[mt][nt][j] = 0.0f;

    const int qr = lane >> 2;
    const int qc = (lane & 3) * 2;

    float4 pAf[2][2];
    uint4  pA[2];
    uint4  pB[2];

    auto prefetch = [&](int kc) {
        if constexpr (AFP32) {
            const float* A = (const float*)A_;
            #pragma unroll
            for (int it = 0; it < 2; it++) {
                int r = (it == 0) ? r0l : r1l;
                if (bm + r < N_NODES) {
                    size_t gi = (size_t)(bm + r) * K + kc + i0l;
                    pAf[it][0] = *(const float4*)(A + gi);
                    pAf[it][1] = *(const float4*)(A + gi + 4);
                } else {
                    pAf[it][0] = make_float4(0.f, 0.f, 0.f, 0.f);
                    pAf[it][1] = make_float4(0.f, 0.f, 0.f, 0.f);
                }
            }
        } else {
            const __half* A = (const __half*)A_;
            #pragma unroll
            for (int it = 0; it < 2; it++) {
                int r = (it == 0) ? r0l : r1l;
                size_t gi = (size_t)(bm + r) * K + kc + i0l;
                pA[it] = *(const uint4*)(A + gi);
            }
        }
        #pragma unroll
        for (int it = 0; it < 2; it++) {
            int r = (it == 0) ? r0l : r1l;
            size_t gi = (size_t)(bn + r) * K + kc + i0l;
            pB[it] = *(const uint4*)(B + gi);
        }
    };

    auto stage = [&]() {
        if constexpr (AFP32) {
            #pragma unroll
            for (int it = 0; it < 2; it++) {
                int r = (it == 0) ? r0l : r1l;
                uint4 v;
                v.x = pack_h2(pAf[it][0].x, pAf[it][0].y);
                v.y = pack_h2(pAf[it][0].z, pAf[it][0].w);
                v.z = pack_h2(pAf[it][1].x, pAf[it][1].y);
                v.w = pack_h2(pAf[it][1].z, pAf[it][1].w);
                *(uint4*)&sA[r * PADK + i0l] = v;
            }
        } else {
            #pragma unroll
            for (int it = 0; it < 2; it++) {
                int r = (it == 0) ? r0l : r1l;
                *(uint4*)&sA[r * PADK + i0l] = pA[it];
            }
        }
        #pragma unroll
        for (int it = 0; it < 2; it++) {
            int r = (it == 0) ? r0l : r1l;
            *(uint4*)&sB[r * PADK + i0l] = pB[it];
        }
    };

    prefetch(0);
    for (int kc = 0; kc < K; kc += 32) {
        stage();
        __syncthreads();
        if (kc + 32 < K) prefetch(kc + 32);   // LDGs overlap with MMAs below

        #pragma unroll
        for (int ks = 0; ks < 2; ks++) {
            const int kb = ks * 16;
            uint32_t ah[2][4];
            #pragma unroll
            for (int mt = 0; mt < 2; mt++) {
                int rr = wm * 32 + mt * 16 + qr;
                #pragma unroll
                for (int h = 0; h < 2; h++) {
                    int r = rr + h * 8;
                    ah[mt][h]     = *(const uint32_t*)&sA[r * PADK + kb + qc];
                    ah[mt][h + 2] = *(const uint32_t*)&sA[r * PADK + kb + qc + 8];
                }
            }
            #pragma unroll
            for (int nt = 0; nt < 8; nt++) {
                int n = wn * 64 + nt * 8 + qr;
                uint32_t b0 = *(const uint32_t*)&sB[n * PADK + kb + qc];
                uint32_t b1 = *(const uint32_t*)&sB[n * PADK + kb + qc + 8];
                #pragma unroll
                for (int mt = 0; mt < 2; mt++)
                    mma_f16(acc[mt][nt], ah[mt][0], ah[mt][1], ah[mt][2], ah[mt][3],
                            b0, b1);
            }
        }
        __syncthreads();
    }

    #pragma unroll
    for (int mt = 0; mt < 2; mt++) {
        #pragma unroll
        for (int nt = 0; nt < 8; nt++) {
            int r0 = bm + wm * 32 + mt * 16 + qr;
            int c0 = bn + wn * 64 + nt * 8 + qc;
            *(uint32_t*)(C + (size_t)r0 * NT + c0) = pack_h2(acc[mt][nt][0], acc[mt][nt][1]);
            *(uint32_t*)(C + (size_t)(r0 + 8) * NT + c0) = pack_h2(acc[mt][nt][2], acc[mt][nt][3]);
        }
    }
}

// ---------------- CSR gather aggregation (fp16 features) ---------------------
// Warp per node; per 32-edge chunk two coalesced LDGs + shfl broadcast.
// MODE 0 (layer 1, F=256): out = fp16(ELU(agg + h/deg + b)) -> a2
// MODE 1 (layer 2, F=128): red-add (agg + h/deg + b)/count[g] directly into out
template <int F, int MODE>
__global__ __launch_bounds__(128) void gather_kernel(
    const int* __restrict__ offs, const int* __restrict__ degi,
    const int* __restrict__ ssrc, const float* __restrict__ swgt,
    const float* __restrict__ dinv,
    const __half* __restrict__ h, const float* __restrict__ bias,
    __half* __restrict__ oh,
    const int* __restrict__ batch, float* __restrict__ out,
    const int* __restrict__ counts)
{
    constexpr int HPL = F / 32;                   // halves per lane: 8 or 4
    int node = blockIdx.x * 4 + (threadIdx.x >> 5);
    int lane = threadIdx.x & 31;
    if (node >= N_NODES) return;

    int start = offs[node];
    int dg    = degi[node];
    float dn  = dinv[node];

    float acc[HPL];
    #pragma unroll
    for (int v = 0; v < HPL; v++) acc[v] = 0.0f;

    auto accum = [&](int s, float w) {
        if constexpr (HPL == 8) {
            uint4 v = __ldg((const uint4*)(h + (size_t)s * F) + lane);
            const __half2* hp = (const __half2*)&v;
            #pragma unroll
            for (int i = 0; i < 4; i++) {
                float2 f = __half22float2(hp[i]);
                acc[2 * i]     += w * f.x;
                acc[2 * i + 1] += w * f.y;
            }
        } else {
            uint2 v = __ldg((const uint2*)(h + (size_t)s * F) + lane);
            const __half2* hp = (const __half2*)&v;
            #pragma unroll
            for (int i = 0; i < 2; i++) {
                float2 f = __half22float2(hp[i]);
                acc[2 * i]     += w * f.x;
                acc[2 * i + 1] += w * f.y;
            }
        }
    };

    for (int base = 0; base < dg; base += 32) {
        int nch = min(32, dg - base);
        int   s_l = 0;
        float w_l = 0.0f;
        if (lane < nch) {
            s_l = __ldg(&ssrc[start + base + lane]);     // coalesced
            w_l = __ldg(&swgt[start + base + lane]);     // coalesced (precomputed)
        }
        #pragma unroll 4
        for (int j = 0; j < nch; j++) {
            int   s = __shfl_sync(0xFFFFFFFFu, s_l, j);
            float w = __shfl_sync(0xFFFFFFFFu, w_l, j);
            accum(s, w);                                 // independent h-row loads
        }
    }

    float sl = dn * dn;      // 1/deg (self-loop weight)
    int col = lane * HPL;
    float selfv[HPL];
    if constexpr (HPL == 8) {
        uint4 v = __ldg((const uint4*)(h + (size_t)node * F) + lane);
        const __half2* hp = (const __half2*)&v;
        #pragma unroll
        for (int i = 0; i < 4; i++) {
            float2 f = __half22float2(hp[i]);
            selfv[2 * i] = f.x; selfv[2 * i + 1] = f.y;
        }
    } else {
        uint2 v = __ldg((const uint2*)(h + (size_t)node * F) + lane);
        const __half2* hp = (const __half2*)&v;
        #pragma unroll
        for (int i = 0; i < 2; i++) {
            float2 f = __half22float2(hp[i]);
            selfv[2 * i] = f.x; selfv[2 * i + 1] = f.y;
        }
    }

    if constexpr (MODE == 0) {
        uint32_t outw[HPL / 2];
        #pragma unroll
        for (int i = 0; i < HPL; i += 2) {
            float r0 = acc[i]     + selfv[i]     * sl + bias[col + i];
            float r1 = acc[i + 1] + selfv[i + 1] * sl + bias[col + i + 1];
            r0 = r0 > 0.f ? r0 : expm1f(r0);
            r1 = r1 > 0.f ? r1 : expm1f(r1);
            outw[i / 2] = pack_h2(r0, r1);
        }
        *(uint4*)(oh + (size_t)node * F + col) =
            make_uint4(outw[0], outw[1], outw[2], outw[3]);
    } else {
        int g = batch[node];
        float ic = 1.0f / fmaxf((float)counts[g], 1.0f);
        float4 bv = *(const float4*)(bias + col);
        float4 r = make_float4((acc[0] + selfv[0] * sl + bv.x) * ic,
                               (acc[1] + selfv[1] * sl + bv.y) * ic,
                               (acc[2] + selfv[2] * sl + bv.z) * ic,
                               (acc[3] + selfv[3] * sl + bv.w) * ic);
        red_add_v4(out + g * F + col, r);
    }
}

__global__ void zero_out_kernel(float* out, int n) {
    int i = blockIdx.x * blockDim.x + threadIdx.x;
    if (i < n) out[i] = 0.0f;
}

// ---------------- launch -----------------------------------------------------
extern "C" void kernel_launch(void* const* d_in, const int* in_sizes, int n_in,
                              void* d_out, int out_size)
{
    const float* x   = nullptr;
    const float* W1  = nullptr;
    const float* b1  = nullptr;
    const float* W2  = nullptr;
    const float* b2  = nullptr;
    const void*  ei  = nullptr;
    const void*  bat = nullptr;

    for (int i = 0; i < n_in; i++) {
        switch (in_sizes[i]) {
            case 12800000: x   = (const float*)d_in[i]; break;
            case 65536:    W1  = (const float*)d_in[i]; break;
            case 256:      b1  = (const float*)d_in[i]; break;
            case 32768:    W2  = (const float*)d_in[i]; break;
            case 128:      b2  = (const float*)d_in[i]; break;
            case 1600000:  ei  = d_in[i];               break;
            case 50000:    bat = d_in[i];               break;
            default: break;
        }
    }
    float* out = (float*)d_out;

    if (!x || !W1 || !b1 || !W2 || !b2 || !ei || !bat) {
        zero_out_kernel<<<(out_size + 255) / 256, 256>>>(out, out_size);
        return;
    }

    void* p;
    cudaGetSymbolAddress(&p, g_dinv);    float* dinv   = (float*)p;
    cudaGetSymbolAddress(&p, g_degi);    int*   degi   = (int*)p;
    cudaGetSymbolAddress(&p, g_offs);    int*   offs   = (int*)p;
    cudaGetSymbolAddress(&p, g_cursor);  int*   cursor = (int*)p;
    cudaGetSymbolAddress(&p, g_partials);int*   parts  = (int*)p;
    cudaGetSymbolAddress(&p, g_ssrc);    int*   ssrc   = (int*)p;
    cudaGetSymbolAddress(&p, g_swgt);    float* swgt   = (float*)p;
    cudaGetSymbolAddress(&p, g_h1);      __half* h1    = (__half*)p;
    cudaGetSymbolAddress(&p, g_h2);      __half* h2    = (__half*)p;
    cudaGetSymbolAddress(&p, g_counts);  int*   counts = (int*)p;
    cudaGetSymbolAddress(&p, g_src);     int*   src    = (int*)p;
    cudaGetSymbolAddress(&p, g_dst);     int*   dst    = (int*)p;
    cudaGetSymbolAddress(&p, g_batch);   int*   batch  = (int*)p;
    cudaGetSymbolAddress(&p, g_oddcnt);  int*   oddc   = (int*)p;
    cudaGetSymbolAddress(&p, g_a2);      __half* a2    = (__half*)p;
    cudaGetSymbolAddress(&p, g_w1t);     __half* w1t   = (__half*)p;
    cudaGetSymbolAddress(&p, g_w2t);     __half* w2t   = (__half*)p;

    // static host-side resources (streams/events are NOT device memory)
    static cudaStream_t s2 = nullptr;
    static cudaEvent_t evFork = nullptr, evJoin = nullptr;
    if (!s2) {
        cudaStreamCreateWithFlags(&s2, cudaStreamNonBlocking);
        cudaEventCreateWithFlags(&evFork, cudaEventDisableTiming);
        cudaEventCreateWithFlags(&evJoin, cudaEventDisableTiming);
    }

    // ---- fork: weights + GEMM1 on s2, independent of the CSR chain ----
    cudaEventRecord(evFork, 0);
    cudaStreamWaitEvent(s2, evFork, 0);

    conv_w_kernel<<<(HID * IN_CH + OUT_CH * HID + 255) / 256, 256, 0, s2>>>(
        W1, W2, w1t, w2t);
    mma_gemm_kernel<HID, true><<<dim3(HID / 128, N_PAD / 128), 256, 0, s2>>>(
        x, w1t, h1);
    cudaEventRecord(evJoin, s2);

    // ---- main stream: CSR build chain ----
    cudaMemsetAsync(degi,   0, N_NODES * sizeof(int));
    cudaMemsetAsync(counts, 0, N_GRAPHS * sizeof(int));
    cudaMemsetAsync(out,    0, N_GRAPHS * OUT_CH * sizeof(float));
    cudaMemsetAsync(oddc,   0, 2 * sizeof(int));

    detect_kernel<<<(825000 + 255) / 256, 256>>>((const int*)ei, (const int*)bat, oddc);
    ei_hist_kernel<<<(N_EDGES + 255) / 256, 256>>>(ei, src, dst, oddc, degi);
    bat_dinv_kernel<<<(N_NODES + 255) / 256, 256>>>(bat, batch, oddc, degi, dinv, counts);
    scan1_kernel<<<SCAN_NB, SCAN_BLK>>>(degi, offs, parts);
    scan2_kernel<<<1, 32>>>(parts);
    scan3_kernel<<<(N_NODES + 255) / 256, 256>>>(offs, cursor, parts);
    scatter_build_kernel<<<(N_EDGES + 255) / 256, 256>>>(src, dst, cursor, ssrc, swgt, dinv);

    // ---- join: gather1 needs both h1 (s2) and CSR (main) ----
    cudaStreamWaitEvent(0, evJoin, 0);

    gather_kernel<HID, 0><<<(N_NODES + 3) / 4, 128>>>(
        offs, degi, ssrc, swgt, dinv, h1, b1, a2, nullptr, nullptr, nullptr);

    mma_gemm_kernel<OUT_CH, false><<<dim3(OUT_CH / 128, N_PAD / 128), 256>>>(a2, w2t, h2);

    // layer-2 gather + bias + mean-pool directly into d_out
    gather_kernel<OUT_CH, 1><<<(N_NODES + 3) / 4, 128>>>(
        offs, degi, ssrc, swgt, dinv, h2, b2, nullptr, batch, out, counts);
}

// round 14
// speedup vs baseline: 1.1954x; 1.1365x over previous
#include <cuda_runtime.h>
#include <cuda_fp16.h>
#include <cstdint>

#define N_NODES 50000
#define N_PAD   50048      // multiple of 128 for MMA tiles
#define N_EDGES 800000
#define IN_CH 256
#define HID 256
#define OUT_CH 128
#define N_GRAPHS 64
#define SCAN_BLK 512
#define SCAN_NB  ((N_NODES + SCAN_BLK - 1) / SCAN_BLK)   // 98

// ---------------- scratch (device globals; no cudaMalloc allowed) ----------
__device__ float g_dinv[N_NODES];
__device__ int   g_degi[N_NODES];
__device__ int   g_offs[N_NODES];
__device__ int   g_cursor[N_NODES];
__device__ int   g_partials[SCAN_NB];
__device__ int   g_ssrc[N_EDGES];
__device__ float g_swgt[N_EDGES];
__device__ __half g_h1[(size_t)N_PAD * HID];
__device__ __half g_h2[(size_t)N_PAD * OUT_CH];
__device__ float g_sums[N_GRAPHS * OUT_CH];
__device__ int   g_counts[N_GRAPHS];
__device__ int   g_src[N_EDGES];
__device__ int   g_dst[N_EDGES];
__device__ int   g_batch[N_NODES];
__device__ int   g_oddcnt[2];             // [0]=edge_index, [1]=batch
// fp16 operands. Pad rows (>= N_NODES) of g_a2 stay zero: zero-initialized
// device globals, never written.
__device__ __half g_a2[(size_t)N_PAD * HID];
__device__ __half g_w1t[HID * IN_CH];     // [n][k] = W1[k][n]
__device__ __half g_w2t[OUT_CH * HID];

// ---------------- helpers ---------------------------------------------------
__device__ __forceinline__ void red_add_v4(float* addr, float4 v) {
    asm volatile("red.global.add.v4.f32 [%0], {%1,%2,%3,%4};"
                 :: "l"(addr), "f"(v.x), "f"(v.y), "f"(v.z), "f"(v.w) : "memory");
}
__device__ __forceinline__ void mma_f16(float* c, uint32_t a0, uint32_t a1,
                                        uint32_t a2, uint32_t a3,
                                        uint32_t b0, uint32_t b1) {
    asm volatile("mma.sync.aligned.m16n8k16.row.col.f32.f16.f16.f32 "
                 "{%0,%1,%2,%3}, {%4,%5,%6,%7}, {%8,%9}, {%0,%1,%2,%3};"
                 : "+f"(c[0]), "+f"(c[1]), "+f"(c[2]), "+f"(c[3])
                 : "r"(a0), "r"(a1), "r"(a2), "r"(a3), "r"(b0), "r"(b1));
}
__device__ __forceinline__ uint32_t pack_h2(float a, float b) {
    __half2 h = __floats2half2_rn(a, b);
    return *reinterpret_cast<uint32_t*>(&h);
}

// ---------------- dtype detection (both buffers, one kernel) -----------------
__global__ void detect_kernel(const int* __restrict__ ei32, const int* __restrict__ bat32,
                              int* __restrict__ cnt) {
    int i = blockIdx.x * blockDim.x + threadIdx.x;
    int local = 0, which = -1;
    if (i < 800000)       { which = 0; local = (ei32[2 * i + 1] != 0); }
    else if (i < 825000)  { which = 1; local = (bat32[2 * (i - 800000) + 1] != 0); }
    unsigned m = __ballot_sync(0xFFFFFFFFu, local);
    if ((threadIdx.x & 31) == 0 && m && which >= 0) atomicAdd(&cnt[which], __popc(m));
}
// fused: edge conversion + degree histogram
__global__ void ei_hist_kernel(const void* __restrict__ ei, int* __restrict__ src,
                               int* __restrict__ dst, const int* __restrict__ cnt,
                               int* __restrict__ degi) {
    int e = blockIdx.x * blockDim.x + threadIdx.x;
    if (e >= N_EDGES) return;
    int s, d;
    if (cnt[0] < 100) { const long long* p = (const long long*)ei; s = (int)p[e]; d = (int)p[N_EDGES + e]; }
    else              { const int* p = (const int*)ei;             s = p[e];      d = p[N_EDGES + e]; }
    s = min(max(s, 0), N_NODES - 1);
    d = min(max(d, 0), N_NODES - 1);
    src[e] = s;
    dst[e] = d;
    atomicAdd(&degi[d], 1);
}
// fused: batch conversion + dinv
__global__ void bat_dinv_kernel(const void* __restrict__ bat, int* __restrict__ batch,
                                const int* __restrict__ cnt,
                                const int* __restrict__ degi, float* __restrict__ dinv) {
    int i = blockIdx.x * blockDim.x + threadIdx.x;
    if (i >= N_NODES) return;
    int g;
    if (cnt[1] < 100) g = (int)((const long long*)bat)[i];
    else              g = ((const int*)bat)[i];
    batch[i] = min(max(g, 0), N_GRAPHS - 1);
    dinv[i] = rsqrtf((float)degi[i] + 1.0f);
}

// ---------------- weight transpose + fp16 convert (both weights) -------------
__global__ void conv_w_kernel(const float* __restrict__ W1, const float* __restrict__ W2,
                              __half* __restrict__ w1t, __half* __restrict__ w2t) {
    int i = blockIdx.x * blockDim.x + threadIdx.x;
    if (i < HID * IN_CH) {
        int n = i / IN_CH, k = i % IN_CH;
        w1t[(size_t)n * IN_CH + k] = __float2half_rn(W1[(size_t)k * HID + n]);
    } else {
        int j = i - HID * IN_CH;
        if (j < OUT_CH * HID) {
            int n = j / HID, k = j % HID;
            w2t[(size_t)n * HID + k] = __float2half_rn(W2[(size_t)k * OUT_CH + n]);
        }
    }
}

// ---------------- CSR scan ----------------------------------------------------
__global__ __launch_bounds__(SCAN_BLK) void scan1_kernel(
    const int* __restrict__ degi, int* __restrict__ offs, int* __restrict__ partials) {
    __shared__ int sm[SCAN_BLK];
    int i = blockIdx.x * SCAN_BLK + threadIdx.x;
    int v = (i < N_NODES) ? degi[i] : 0;
    sm[threadIdx.x] = v;
    __syncthreads();
    for (int d = 1; d < SCAN_BLK; d <<= 1) {
        int t = (threadIdx.x >= d) ? sm[threadIdx.x - d] : 0;
        __syncthreads();
        sm[threadIdx.x] += t;
        __syncthreads();
    }
    if (i < N_NODES) offs[i] = sm[threadIdx.x] - v;       // exclusive
    if (threadIdx.x == SCAN_BLK - 1) partials[blockIdx.x] = sm[SCAN_BLK - 1];
}
// single-warp shfl scan over SCAN_NB partials (exclusive)
__global__ void scan2_kernel(int* __restrict__ partials) {
    int lane = threadIdx.x;
    int run = 0;
    for (int b = 0; b < SCAN_NB; b += 32) {
        int idx = b + lane;
        int orig = (idx < SCAN_NB) ? partials[idx] : 0;
        int v = orig;
        #pragma unroll
        for (int d = 1; d < 32; d <<= 1) {
            int t = __shfl_up_sync(0xFFFFFFFFu, v, d);
            if (lane >= d) v += t;
        }
        if (idx < SCAN_NB) partials[idx] = run + v - orig;   // exclusive
        run += __shfl_sync(0xFFFFFFFFu, v, 31);
    }
}
__global__ void scan3_kernel(int* __restrict__ offs, int* __restrict__ cursor,
                             const int* __restrict__ partials) {
    int i = blockIdx.x * blockDim.x + threadIdx.x;
    if (i < N_NODES) {
        int o = offs[i] + partials[i / SCAN_BLK];
        offs[i] = o;
        cursor[i] = o;
    }
}
// build sorted src + precomputed edge weight dinv[s]*dinv[d]
__global__ void scatter_build_kernel(const int* __restrict__ src, const int* __restrict__ dst,
                                     int* __restrict__ cursor, int* __restrict__ ssrc,
                                     float* __restrict__ swgt,
                                     const float* __restrict__ dinv) {
    int e = blockIdx.x * blockDim.x + threadIdx.x;
    if (e >= N_EDGES) return;
    int s = src[e], d = dst[e];
    int pos = atomicAdd(&cursor[d], 1);
    ssrc[pos] = s;
    swgt[pos] = dinv[s] * dinv[d];
}

// ---------------- HMMA GEMM: C[Mpad,NT] = A[Mpad,256] @ Wt[NT,256]^T --------
#define PADK 40
template <int NT, bool AFP32>
__global__ __launch_bounds__(256) void mma_gemm_kernel(
    const void* __restrict__ A_,
    const __half* __restrict__ B,
    __half* __restrict__ C)
{
    constexpr int K = 256;
    __shared__ __align__(16) __half sA[128 * PADK];
    __shared__ __align__(16) __half sB[128 * PADK];

    const int tid  = threadIdx.x;
    const int lane = tid & 31;
    const int wid  = tid >> 5;
    const int wm   = wid & 3;
    const int wn   = wid >> 2;
    const int bm   = blockIdx.y * 128;
    const int bn   = blockIdx.x * 128;

    const int r0l = tid >> 2, i0l = (tid & 3) * 8;
    const int r1l = r0l + 64;

    float acc[2][8][4];
    #pragma unroll
    for (int mt = 0; mt < 2; mt++)
        #pragma unroll
        for (int nt = 0; nt < 8; nt++)
            #pragma unroll
            for (int j = 0; j < 4; j++) acc[mt][nt][j] = 0.0f;

    const int qr = lane >> 2;
    const int qc = (lane & 3) * 2;

    float4 pAf[2][2];
    uint4  pA[2];
    uint4  pB[2];

    auto prefetch = [&](int kc) {
        if constexpr (AFP32) {
            const float* A = (const float*)A_;
            #pragma unroll
            for (int it = 0; it < 2; it++) {
                int r = (it == 0) ? r0l : r1l;
                if (bm + r < N_NODES) {
                    size_t gi = (size_t)(bm + r) * K + kc + i0l;
                    pAf[it][0] = *(const float4*)(A + gi);
                    pAf[it][1] = *(const float4*)(A + gi + 4);
                } else {
                    pAf[it][0] = make_float4(0.f, 0.f, 0.f, 0.f);
                    pAf[it][1] = make_float4(0.f, 0.f, 0.f, 0.f);
                }
            }
        } else {
            const __half* A = (const __half*)A_;
            #pragma unroll
            for (int it = 0; it < 2; it++) {
                int r = (it == 0) ? r0l : r1l;
                size_t gi = (size_t)(bm + r) * K + kc + i0l;
                pA[it] = *(const uint4*)(A + gi);
            }
        }
        #pragma unroll
        for (int it = 0; it < 2; it++) {
            int r = (it == 0) ? r0l : r1l;
            size_t gi = (size_t)(bn + r) * K + kc + i0l;
            pB[it] = *(const uint4*)(B + gi);
        }
    };

    auto stage = [&]() {
        if constexpr (AFP32) {
            #pragma unroll
            for (int it = 0; it < 2; it++) {
                int r = (it == 0) ? r0l : r1l;
                uint4 v;
                v.x = pack_h2(pAf[it][0].x, pAf[it][0].y);
                v.y = pack_h2(pAf[it][0].z, pAf[it][0].w);
                v.z = pack_h2(pAf[it][1].x, pAf[it][1].y);
                v.w = pack_h2(pAf[it][1].z, pAf[it][1].w);
                *(uint4*)&sA[r * PADK + i0l] = v;
            }
        } else {
            #pragma unroll
            for (int it = 0; it < 2; it++) {
                int r = (it == 0) ? r0l : r1l;
                *(uint4*)&sA[r * PADK + i0l] = pA[it];
            }
        }
        #pragma unroll
        for (int it = 0; it < 2; it++) {
            int r = (it == 0) ? r0l : r1l;
            *(uint4*)&sB[r * PADK + i0l] = pB[it];
        }
    };

    prefetch(0);
    for (int kc = 0; kc < K; kc += 32) {
        stage();
        __syncthreads();
        if (kc + 32 < K) prefetch(kc + 32);   // LDGs overlap with MMAs below

        #pragma unroll
        for (int ks = 0; ks < 2; ks++) {
            const int kb = ks * 16;
            uint32_t ah[2][4];
            #pragma unroll
            for (int mt = 0; mt < 2; mt++) {
                int rr = wm * 32 + mt * 16 + qr;
                #pragma unroll
                for (int h = 0; h < 2; h++) {
                    int r = rr + h * 8;
                    ah[mt][h]     = *(const uint32_t*)&sA[r * PADK + kb + qc];
                    ah[mt][h + 2] = *(const uint32_t*)&sA[r * PADK + kb + qc + 8];
                }
            }
            #pragma unroll
            for (int nt = 0; nt < 8; nt++) {
                int n = wn * 64 + nt * 8 + qr;
                uint32_t b0 = *(const uint32_t*)&sB[n * PADK + kb + qc];
                uint32_t b1 = *(const uint32_t*)&sB[n * PADK + kb + qc + 8];
                #pragma unroll
                for (int mt = 0; mt < 2; mt++)
                    mma_f16(acc[mt][nt], ah[mt][0], ah[mt][1], ah[mt][2], ah[mt][3],
                            b0, b1);
            }
        }
        __syncthreads();
    }

    #pragma unroll
    for (int mt = 0; mt < 2; mt++) {
        #pragma unroll
        for (int nt = 0; nt < 8; nt++) {
            int r0 = bm + wm * 32 + mt * 16 + qr;
            int c0 = bn + wn * 64 + nt * 8 + qc;
            *(uint32_t*)(C + (size_t)r0 * NT + c0) = pack_h2(acc[mt][nt][0], acc[mt][nt][1]);
            *(uint32_t*)(C + (size_t)(r0 + 8) * NT + c0) = pack_h2(acc[mt][nt][2], acc[mt][nt][3]);
        }
    }
}

// ---------------- CSR gather aggregation (fp16 features) ---------------------
// Warp per node; per 32-edge chunk two coalesced LDGs + shfl broadcast.
// MODE 0 (layer 1, F=256): out = fp16(ELU(agg + h/deg + b)) -> a2
// MODE 1 (layer 2, F=128): red-add (agg + h/deg + b) into sums[batch[node]]
template <int F, int MODE>
__global__ __launch_bounds__(128) void gather_kernel(
    const int* __restrict__ offs, const int* __restrict__ degi,
    const int* __restrict__ ssrc, const float* __restrict__ swgt,
    const float* __restrict__ dinv,
    const __half* __restrict__ h, const float* __restrict__ bias,
    __half* __restrict__ oh,
    const int* __restrict__ batch, float* __restrict__ sums,
    int* __restrict__ counts)
{
    constexpr int HPL = F / 32;                   // halves per lane: 8 or 4
    int node = blockIdx.x * 4 + (threadIdx.x >> 5);
    int lane = threadIdx.x & 31;
    if (node >= N_NODES) return;

    int start = offs[node];
    int dg    = degi[node];
    float dn  = dinv[node];

    float acc[HPL];
    #pragma unroll
    for (int v = 0; v < HPL; v++) acc[v] = 0.0f;

    auto accum = [&](int s, float w) {
        if constexpr (HPL == 8) {
            uint4 v = __ldg((const uint4*)(h + (size_t)s * F) + lane);
            const __half2* hp = (const __half2*)&v;
            #pragma unroll
            for (int i = 0; i < 4; i++) {
                float2 f = __half22float2(hp[i]);
                acc[2 * i]     += w * f.x;
                acc[2 * i + 1] += w * f.y;
            }
        } else {
            uint2 v = __ldg((const uint2*)(h + (size_t)s * F) + lane);
            const __half2* hp = (const __half2*)&v;
            #pragma unroll
            for (int i = 0; i < 2; i++) {
                float2 f = __half22float2(hp[i]);
                acc[2 * i]     += w * f.x;
                acc[2 * i + 1] += w * f.y;
            }
        }
    };

    for (int base = 0; base < dg; base += 32) {
        int nch = min(32, dg - base);
        int   s_l = 0;
        float w_l = 0.0f;
        if (lane < nch) {
            s_l = __ldg(&ssrc[start + base + lane]);     // coalesced
            w_l = __ldg(&swgt[start + base + lane]);     // coalesced (precomputed)
        }
        #pragma unroll 4
        for (int j = 0; j < nch; j++) {
            int   s = __shfl_sync(0xFFFFFFFFu, s_l, j);
            float w = __shfl_sync(0xFFFFFFFFu, w_l, j);
            accum(s, w);                                 // independent h-row loads
        }
    }

    float sl = dn * dn;      // 1/deg (self-loop weight)
    int col = lane * HPL;
    float selfv[HPL];
    if constexpr (HPL == 8) {
        uint4 v = __ldg((const uint4*)(h + (size_t)node * F) + lane);
        const __half2* hp = (const __half2*)&v;
        #pragma unroll
        for (int i = 0; i < 4; i++) {
            float2 f = __half22float2(hp[i]);
            selfv[2 * i] = f.x; selfv[2 * i + 1] = f.y;
        }
    } else {
        uint2 v = __ldg((const uint2*)(h + (size_t)node * F) + lane);
        const __half2* hp = (const __half2*)&v;
        #pragma unroll
        for (int i = 0; i < 2; i++) {
            float2 f = __half22float2(hp[i]);
            selfv[2 * i] = f.x; selfv[2 * i + 1] = f.y;
        }
    }

    if constexpr (MODE == 0) {
        uint32_t outw[HPL / 2];
        #pragma unroll
        for (int i = 0; i < HPL; i += 2) {
            float r0 = acc[i]     + selfv[i]     * sl + bias[col + i];
            float r1 = acc[i + 1] + selfv[i + 1] * sl + bias[col + i + 1];
            r0 = r0 > 0.f ? r0 : expm1f(r0);
            r1 = r1 > 0.f ? r1 : expm1f(r1);
            outw[i / 2] = pack_h2(r0, r1);
        }
        *(uint4*)(oh + (size_t)node * F + col) =
            make_uint4(outw[0], outw[1], outw[2], outw[3]);
    } else {
        int g = batch[node];
        float4 bv = *(const float4*)(bias + col);
        float4 r = make_float4(acc[0] + selfv[0] * sl + bv.x,
                               acc[1] + selfv[1] * sl + bv.y,
                               acc[2] + selfv[2] * sl + bv.z,
                               acc[3] + selfv[3] * sl + bv.w);
        red_add_v4(sums + g * F + col, r);
        if (lane == 0) atomicAdd(&counts[g], 1);
    }
}

__global__ void pool_final_kernel(const float* __restrict__ sums,
                                  const int* __restrict__ counts,
                                  float* __restrict__ out)
{
    int c = blockIdx.x * blockDim.x + threadIdx.x;
    if (c < N_GRAPHS * OUT_CH) {
        int g = c / OUT_CH;
        float cnt = fmaxf((float)counts[g], 1.0f);
        out[c] = sums[c] / cnt;
    }
}

__global__ void zero_out_kernel(float* out, int n) {
    int i = blockIdx.x * blockDim.x + threadIdx.x;
    if (i < n) out[i] = 0.0f;
}

// ---------------- launch -----------------------------------------------------
extern "C" void kernel_launch(void* const* d_in, const int* in_sizes, int n_in,
                              void* d_out, int out_size)
{
    const float* x   = nullptr;
    const float* W1  = nullptr;
    const float* b1  = nullptr;
    const float* W2  = nullptr;
    const float* b2  = nullptr;
    const void*  ei  = nullptr;
    const void*  bat = nullptr;

    for (int i = 0; i < n_in; i++) {
        switch (in_sizes[i]) {
            case 12800000: x   = (const float*)d_in[i]; break;
            case 65536:    W1  = (const float*)d_in[i]; break;
            case 256:      b1  = (const float*)d_in[i]; break;
            case 32768:    W2  = (const float*)d_in[i]; break;
            case 128:      b2  = (const float*)d_in[i]; break;
            case 1600000:  ei  = d_in[i];               break;
            case 50000:    bat = d_in[i];               break;
            default: break;
        }
    }
    float* out = (float*)d_out;

    if (!x || !W1 || !b1 || !W2 || !b2 || !ei || !bat) {
        zero_out_kernel<<<(out_size + 255) / 256, 256>>>(out, out_size);
        return;
    }

    void* p;
    cudaGetSymbolAddress(&p, g_dinv);    float* dinv   = (float*)p;
    cudaGetSymbolAddress(&p, g_degi);    int*   degi   = (int*)p;
    cudaGetSymbolAddress(&p, g_offs);    int*   offs   = (int*)p;
    cudaGetSymbolAddress(&p, g_cursor);  int*   cursor = (int*)p;
    cudaGetSymbolAddress(&p, g_partials);int*   parts  = (int*)p;
    cudaGetSymbolAddress(&p, g_ssrc);    int*   ssrc   = (int*)p;
    cudaGetSymbolAddress(&p, g_swgt);    float* swgt   = (float*)p;
    cudaGetSymbolAddress(&p, g_h1);      __half* h1    = (__half*)p;
    cudaGetSymbolAddress(&p, g_h2);      __half* h2    = (__half*)p;
    cudaGetSymbolAddress(&p, g_sums);    float* sums   = (float*)p;
    cudaGetSymbolAddress(&p, g_counts);  int*   counts = (int*)p;
    cudaGetSymbolAddress(&p, g_src);     int*   src    = (int*)p;
    cudaGetSymbolAddress(&p, g_dst);     int*   dst    = (int*)p;
    cudaGetSymbolAddress(&p, g_batch);   int*   batch  = (int*)p;
    cudaGetSymbolAddress(&p, g_oddcnt);  int*   oddc   = (int*)p;
    cudaGetSymbolAddress(&p, g_a2);      __half* a2    = (__half*)p;
    cudaGetSymbolAddress(&p, g_w1t);     __half* w1t   = (__half*)p;
    cudaGetSymbolAddress(&p, g_w2t);     __half* w2t   = (__half*)p;

    // static host-side resources (streams/events are NOT device memory)
    static cudaStream_t s2 = nullptr;
    static cudaEvent_t evFork = nullptr, evJoin = nullptr;
    if (!s2) {
        cudaStreamCreateWithFlags(&s2, cudaStreamNonBlocking);
        cudaEventCreateWithFlags(&evFork, cudaEventDisableTiming);
        cudaEventCreateWithFlags(&evJoin, cudaEventDisableTiming);
    }

    // ---- fork: weights + GEMM1 on s2, independent of the CSR chain ----
    cudaEventRecord(evFork, 0);
    cudaStreamWaitEvent(s2, evFork, 0);

    conv_w_kernel<<<(HID * IN_CH + OUT_CH * HID + 255) / 256, 256, 0, s2>>>(
        W1, W2, w1t, w2t);
    mma_gemm_kernel<HID, true><<<dim3(HID / 128, N_PAD / 128), 256, 0, s2>>>(
        x, w1t, h1);
    cudaEventRecord(evJoin, s2);

    // ---- main stream: CSR build chain ----
    cudaMemsetAsync(oddc, 0, 2 * sizeof(int));
    cudaMemsetAsync(degi,   0, N_NODES * sizeof(int));
    cudaMemsetAsync(sums,   0, N_GRAPHS * OUT_CH * sizeof(float));
    cudaMemsetAsync(counts, 0, N_GRAPHS * sizeof(int));

    detect_kernel<<<(825000 + 255) / 256, 256>>>((const int*)ei, (const int*)bat, oddc);
    ei_hist_kernel<<<(N_EDGES + 255) / 256, 256>>>(ei, src, dst, oddc, degi);
    bat_dinv_kernel<<<(N_NODES + 255) / 256, 256>>>(bat, batch, oddc, degi, dinv);
    scan1_kernel<<<SCAN_NB, SCAN_BLK>>>(degi, offs, parts);
    scan2_kernel<<<1, 32>>>(parts);
    scan3_kernel<<<(N_NODES + 255) / 256, 256>>>(offs, cursor, parts);
    scatter_build_kernel<<<(N_EDGES + 255) / 256, 256>>>(src, dst, cursor, ssrc, swgt, dinv);

    // ---- join: gather1 needs both h1 (s2) and CSR (main) ----
    cudaStreamWaitEvent(0, evJoin, 0);

    gather_kernel<HID, 0><<<(N_NODES + 3) / 4, 128>>>(
        offs, degi, ssrc, swgt, dinv, h1, b1, a2, nullptr, nullptr, nullptr);

    mma_gemm_kernel<OUT_CH, false><<<dim3(OUT_CH / 128, N_PAD / 128), 256>>>(a2, w2t, h2);

    gather_kernel<OUT_CH, 1><<<(N_NODES + 3) / 4, 128>>>(
        offs, degi, ssrc, swgt, dinv, h2, b2, nullptr, batch, sums, counts);

    pool_final_kernel<<<(N_GRAPHS * OUT_CH + 255) / 256, 256>>>(sums, counts, out);
}

// round 15
// speedup vs baseline: 1.2499x; 1.0456x over previous
#include <cuda_runtime.h>
#include <cuda_fp16.h>
#include <cstdint>

#define N_NODES 50000
#define N_PAD   50048      // multiple of 128 for MMA tiles
#define N_EDGES 800000
#define IN_CH 256
#define HID 256
#define OUT_CH 128
#define N_GRAPHS 64
#define SCAN_BLK 512
#define SCAN_NB  ((N_NODES + SCAN_BLK - 1) / SCAN_BLK)   // 98
#define CW    50176        // coeff row width (multiple of 512)
#define KCH   512          // mgemm K per CTA
#define KSPLIT (CW / KCH)  // 98

// ---------------- scratch (device globals; no cudaMalloc allowed) ----------
__device__ float g_dinv[N_NODES];
__device__ int   g_degi[N_NODES];
__device__ int   g_offs[N_NODES];
__device__ int   g_cursor[N_NODES];
__device__ int   g_partials[SCAN_NB];
__device__ int   g_ssrc[N_EDGES];
__device__ float g_swgt[N_EDGES];
__device__ __half g_h1[(size_t)N_PAD * HID];
__device__ int   g_counts[N_GRAPHS];
__device__ int   g_src[N_EDGES];
__device__ int   g_dst[N_EDGES];
__device__ int   g_batch[N_NODES];
__device__ int   g_oddcnt[2];             // [0]=edge_index, [1]=batch
// fp16 operands. Pad rows (>= N_NODES / >= used range) stay zero:
// zero-initialized device globals, never written.
__device__ __half g_a2[(size_t)N_PAD * HID];
__device__ __half g_w1t[HID * IN_CH];     // [n][k] = W1[k][n]
__device__ float  g_coeff32[(size_t)N_GRAPHS * CW];
__device__ __half g_coeff16[(size_t)N_GRAPHS * CW];
__device__ float  g_M32[N_GRAPHS * HID];  // 64 x 256 fp32

// ---------------- helpers ---------------------------------------------------
__device__ __forceinline__ void red_add_f32(float* addr, float v) {
    asm volatile("red.global.add.f32 [%0], %1;" :: "l"(addr), "f"(v) : "memory");
}
__device__ __forceinline__ void mma_f16(float* c, uint32_t a0, uint32_t a1,
                                        uint32_t a2, uint32_t a3,
                                        uint32_t b0, uint32_t b1) {
    asm volatile("mma.sync.aligned.m16n8k16.row.col.f32.f16.f16.f32 "
                 "{%0,%1,%2,%3}, {%4,%5,%6,%7}, {%8,%9}, {%0,%1,%2,%3};"
                 : "+f"(c[0]), "+f"(c[1]), "+f"(c[2]), "+f"(c[3])
                 : "r"(a0), "r"(a1), "r"(a2), "r"(a3), "r"(b0), "r"(b1));
}
__device__ __forceinline__ uint32_t pack_h2(float a, float b) {
    __half2 h = __floats2half2_rn(a, b);
    return *reinterpret_cast<uint32_t*>(&h);
}

// ---------------- dtype detection (both buffers, one kernel) -----------------
__global__ void detect_kernel(const int* __restrict__ ei32, const int* __restrict__ bat32,
                              int* __restrict__ cnt) {
    int i = blockIdx.x * blockDim.x + threadIdx.x;
    int local = 0, which = -1;
    if (i < 800000)       { which = 0; local = (ei32[2 * i + 1] != 0); }
    else if (i < 825000)  { which = 1; local = (bat32[2 * (i - 800000) + 1] != 0); }
    unsigned m = __ballot_sync(0xFFFFFFFFu, local);
    if ((threadIdx.x & 31) == 0 && m && which >= 0) atomicAdd(&cnt[which], __popc(m));
}
// fused: edge conversion + degree histogram
__global__ void ei_hist_kernel(const void* __restrict__ ei, int* __restrict__ src,
                               int* __restrict__ dst, const int* __restrict__ cnt,
                               int* __restrict__ degi) {
    int e = blockIdx.x * blockDim.x + threadIdx.x;
    if (e >= N_EDGES) return;
    int s, d;
    if (cnt[0] < 100) { const long long* p = (const long long*)ei; s = (int)p[e]; d = (int)p[N_EDGES + e]; }
    else              { const int* p = (const int*)ei;             s = p[e];      d = p[N_EDGES + e]; }
    s = min(max(s, 0), N_NODES - 1);
    d = min(max(d, 0), N_NODES - 1);
    src[e] = s;
    dst[e] = d;
    atomicAdd(&degi[d], 1);
}
// fused: batch conversion + dinv + warp-aggregated per-graph node counts
__global__ void bat_dinv_kernel(const void* __restrict__ bat, int* __restrict__ batch,
                                const int* __restrict__ cnt,
                                const int* __restrict__ degi, float* __restrict__ dinv,
                                int* __restrict__ counts) {
    int i = blockIdx.x * blockDim.x + threadIdx.x;
    int lane = threadIdx.x & 31;
    bool active = (i < N_NODES);
    int g = -1;
    if (active) {
        if (cnt[1] < 100) g = (int)((const long long*)bat)[i];
        else              g = ((const int*)bat)[i];
        g = min(max(g, 0), N_GRAPHS - 1);
        batch[i] = g;
        dinv[i] = rsqrtf((float)degi[i] + 1.0f);
    }
    // warp-aggregated counts (batch is sorted; runs are long)
    int prev = __shfl_up_sync(0xFFFFFFFFu, g, 1);
    bool head = (lane == 0) || (prev != g);
    unsigned heads = __ballot_sync(0xFFFFFFFFu, head);
    if (active && head) {
        unsigned above = (lane < 31) ? (heads >> (lane + 1)) : 0u;
        int nxt = above ? (lane + 1 + (__ffs(above) - 1)) : 32;
        // cap run at last active lane in this warp's index range
        int limit = min(32, N_NODES - (i - lane));
        if (nxt > limit) nxt = limit;
        atomicAdd(&counts[g], nxt - lane);
    }
}

// ---------------- weight transpose + fp16 convert (W1 only) ------------------
__global__ void conv_w_kernel(const float* __restrict__ W1, __half* __restrict__ w1t) {
    int i = blockIdx.x * blockDim.x + threadIdx.x;
    if (i < HID * IN_CH) {
        int n = i / IN_CH, k = i % IN_CH;
        w1t[(size_t)n * IN_CH + k] = __float2half_rn(W1[(size_t)k * HID + n]);
    }
}

// ---------------- layer-2 coeff matrix build ----------------------------------
__global__ void coeff_edge_kernel(const int* __restrict__ src, const int* __restrict__ dst,
                                  const int* __restrict__ batch,
                                  const float* __restrict__ dinv,
                                  float* __restrict__ c32) {
    int e = blockIdx.x * blockDim.x + threadIdx.x;
    if (e >= N_EDGES) return;
    int s = src[e], d = dst[e];
    atomicAdd(&c32[(size_t)batch[d] * CW + s], dinv[s] * dinv[d]);
}
__global__ void coeff_self_kernel(const int* __restrict__ batch,
                                  const float* __restrict__ dinv,
                                  float* __restrict__ c32) {
    int j = blockIdx.x * blockDim.x + threadIdx.x;
    if (j >= N_NODES) return;
    float dn = dinv[j];
    c32[(size_t)batch[j] * CW + j] += dn * dn;   // unique index per j: no atomic needed
}
__global__ void coeff_conv_kernel(const float* __restrict__ c32,
                                  __half* __restrict__ c16) {
    size_t i = (size_t)blockIdx.x * blockDim.x + threadIdx.x;
    if (i < (size_t)N_GRAPHS * CW) c16[i] = __float2half_rn(c32[i]);
}

// ---------------- CSR scan ----------------------------------------------------
__global__ __launch_bounds__(SCAN_BLK) void scan1_kernel(
    const int* __restrict__ degi, int* __restrict__ offs, int* __restrict__ partials) {
    __shared__ int sm[SCAN_BLK];
    int i = blockIdx.x * SCAN_BLK + threadIdx.x;
    int v = (i < N_NODES) ? degi[i] : 0;
    sm[threadIdx.x] = v;
    __syncthreads();
    for (int d = 1; d < SCAN_BLK; d <<= 1) {
        int t = (threadIdx.x >= d) ? sm[threadIdx.x - d] : 0;
        __syncthreads();
        sm[threadIdx.x] += t;
        __syncthreads();
    }
    if (i < N_NODES) offs[i] = sm[threadIdx.x] - v;       // exclusive
    if (threadIdx.x == SCAN_BLK - 1) partials[blockIdx.x] = sm[SCAN_BLK - 1];
}
__global__ void scan2_kernel(int* __restrict__ partials) {
    int lane = threadIdx.x;
    int run = 0;
    for (int b = 0; b < SCAN_NB; b += 32) {
        int idx = b + lane;
        int orig = (idx < SCAN_NB) ? partials[idx] : 0;
        int v = orig;
        #pragma unroll
        for (int d = 1; d < 32; d <<= 1) {
            int t = __shfl_up_sync(0xFFFFFFFFu, v, d);
            if (lane >= d) v += t;
        }
        if (idx < SCAN_NB) partials[idx] = run + v - orig;   // exclusive
        run += __shfl_sync(0xFFFFFFFFu, v, 31);
    }
}
__global__ void scan3_kernel(int* __restrict__ offs, int* __restrict__ cursor,
                             const int* __restrict__ partials) {
    int i = blockIdx.x * blockDim.x + threadIdx.x;
    if (i < N_NODES) {
        int o = offs[i] + partials[i / SCAN_BLK];
        offs[i] = o;
        cursor[i] = o;
    }
}
__global__ void scatter_build_kernel(const int* __restrict__ src, const int* __restrict__ dst,
                                     int* __restrict__ cursor, int* __restrict__ ssrc,
                                     float* __restrict__ swgt,
                                     const float* __restrict__ dinv) {
    int e = blockIdx.x * blockDim.x + threadIdx.x;
    if (e >= N_EDGES) return;
    int s = src[e], d = dst[e];
    int pos = atomicAdd(&cursor[d], 1);
    ssrc[pos] = s;
    swgt[pos] = dinv[s] * dinv[d];
}

// ---------------- HMMA GEMM1: h1[Mpad,256] = x @ W1 (A fp32 -> fp16) --------
#define PADK 40
__global__ __launch_bounds__(256) void mma_gemm_kernel(
    const float* __restrict__ A,
    const __half* __restrict__ B,
    __half* __restrict__ C)
{
    constexpr int NT = HID;
    constexpr int K = 256;
    __shared__ __align__(16) __half sA[128 * PADK];
    __shared__ __align__(16) __half sB[128 * PADK];

    const int tid  = threadIdx.x;
    const int lane = tid & 31;
    const int wid  = tid >> 5;
    const int wm   = wid & 3;
    const int wn   = wid >> 2;
    const int bm   = blockIdx.y * 128;
    const int bn   = blockIdx.x * 128;

    const int r0l = tid >> 2, i0l = (tid & 3) * 8;
    const int r1l = r0l + 64;

    float acc[2][8][4];
    #pragma unroll
    for (int mt = 0; mt < 2; mt++)
        #pragma unroll
        for (int nt = 0; nt < 8; nt++)
            #pragma unroll
            for (int j = 0; j < 4; j++) acc[mt][nt][j] = 0.0f;

    const int qr = lane >> 2;
    const int qc = (lane & 3) * 2;

    float4 pAf[2][2];
    uint4  pB[2];

    auto prefetch = [&](int kc) {
        #pragma unroll
        for (int it = 0; it < 2; it++) {
            int r = (it == 0) ? r0l : r1l;
            if (bm + r < N_NODES) {
                size_t gi = (size_t)(bm + r) * K + kc + i0l;
                pAf[it][0] = *(const float4*)(A + gi);
                pAf[it][1] = *(const float4*)(A + gi + 4);
            } else {
                pAf[it][0] = make_float4(0.f, 0.f, 0.f, 0.f);
                pAf[it][1] = make_float4(0.f, 0.f, 0.f, 0.f);
            }
        }
        #pragma unroll
        for (int it = 0; it < 2; it++) {
            int r = (it == 0) ? r0l : r1l;
            size_t gi = (size_t)(bn + r) * K + kc + i0l;
            pB[it] = *(const uint4*)(B + gi);
        }
    };

    auto stage = [&]() {
        #pragma unroll
        for (int it = 0; it < 2; it++) {
            int r = (it == 0) ? r0l : r1l;
            uint4 v;
            v.x = pack_h2(pAf[it][0].x, pAf[it][0].y);
            v.y = pack_h2(pAf[it][0].z, pAf[it][0].w);
            v.z = pack_h2(pAf[it][1].x, pAf[it][1].y);
            v.w = pack_h2(pAf[it][1].z, pAf[it][1].w);
            *(uint4*)&sA[r * PADK + i0l] = v;
        }
        #pragma unroll
        for (int it = 0; it < 2; it++) {
            int r = (it == 0) ? r0l : r1l;
            *(uint4*)&sB[r * PADK + i0l] = pB[it];
        }
    };

    prefetch(0);
    for (int kc = 0; kc < K; kc += 32) {
        stage();
        __syncthreads();
        if (kc + 32 < K) prefetch(kc + 32);

        #pragma unroll
        for (int ks = 0; ks < 2; ks++) {
            const int kb = ks * 16;
            uint32_t ah[2][4];
            #pragma unroll
            for (int mt = 0; mt < 2; mt++) {
                int rr = wm * 32 + mt * 16 + qr;
                #pragma unroll
                for (int h = 0; h < 2; h++) {
                    int r = rr + h * 8;
                    ah[mt][h]     = *(const uint32_t*)&sA[r * PADK + kb + qc];
                    ah[mt][h + 2] = *(const uint32_t*)&sA[r * PADK + kb + qc + 8];
                }
            }
            #pragma unroll
            for (int nt = 0; nt < 8; nt++) {
                int n = wn * 64 + nt * 8 + qr;
                uint32_t b0 = *(const uint32_t*)&sB[n * PADK + kb + qc];
                uint32_t b1 = *(const uint32_t*)&sB[n * PADK + kb + qc + 8];
                #pragma unroll
                for (int mt = 0; mt < 2; mt++)
                    mma_f16(acc[mt][nt], ah[mt][0], ah[mt][1], ah[mt][2], ah[mt][3],
                            b0, b1);
            }
        }
        __syncthreads();
    }

    #pragma unroll
    for (int mt = 0; mt < 2; mt++) {
        #pragma unroll
        for (int nt = 0; nt < 8; nt++) {
            int r0 = bm + wm * 32 + mt * 16 + qr;
            int c0 = bn + wn * 64 + nt * 8 + qc;
            *(uint32_t*)(C + (size_t)r0 * NT + c0) = pack_h2(acc[mt][nt][0], acc[mt][nt][1]);
            *(uint32_t*)(C + (size_t)(r0 + 8) * NT + c0) = pack_h2(acc[mt][nt][2], acc[mt][nt][3]);
        }
    }
}

// ---------------- CSR gather layer 1 (fp16 h1 -> fp16 a2) --------------------
__global__ __launch_bounds__(128) void gather1_kernel(
    const int* __restrict__ offs, const int* __restrict__ degi,
    const int* __restrict__ ssrc, const float* __restrict__ swgt,
    const float* __restrict__ dinv,
    const __half* __restrict__ h, const float* __restrict__ bias,
    __half* __restrict__ oh)
{
    constexpr int F = HID;
    int node = blockIdx.x * 4 + (threadIdx.x >> 5);
    int lane = threadIdx.x & 31;
    if (node >= N_NODES) return;

    int start = offs[node];
    int dg    = degi[node];
    float dn  = dinv[node];

    float acc[8];
    #pragma unroll
    for (int v = 0; v < 8; v++) acc[v] = 0.0f;

    auto accum = [&](int s, float w) {
        uint4 v = __ldg((const uint4*)(h + (size_t)s * F) + lane);
        const __half2* hp = (const __half2*)&v;
        #pragma unroll
        for (int i = 0; i < 4; i++) {
            float2 f = __half22float2(hp[i]);
            acc[2 * i]     += w * f.x;
            acc[2 * i + 1] += w * f.y;
        }
    };

    for (int base = 0; base < dg; base += 32) {
        int nch = min(32, dg - base);
        int   s_l = 0;
        float w_l = 0.0f;
        if (lane < nch) {
            s_l = __ldg(&ssrc[start + base + lane]);
            w_l = __ldg(&swgt[start + base + lane]);
        }
        #pragma unroll 4
        for (int j = 0; j < nch; j++) {
            int   s = __shfl_sync(0xFFFFFFFFu, s_l, j);
            float w = __shfl_sync(0xFFFFFFFFu, w_l, j);
            accum(s, w);
        }
    }

    float sl = dn * dn;
    int col = lane * 8;
    float selfv[8];
    {
        uint4 v = __ldg((const uint4*)(h + (size_t)node * F) + lane);
        const __half2* hp = (const __half2*)&v;
        #pragma unroll
        for (int i = 0; i < 4; i++) {
            float2 f = __half22float2(hp[i]);
            selfv[2 * i] = f.x; selfv[2 * i + 1] = f.y;
        }
    }

    uint32_t outw[4];
    #pragma unroll
    for (int i = 0; i < 8; i += 2) {
        float r0 = acc[i]     + selfv[i]     * sl + bias[col + i];
        float r1 = acc[i + 1] + selfv[i + 1] * sl + bias[col + i + 1];
        r0 = r0 > 0.f ? r0 : expm1f(r0);
        r1 = r1 > 0.f ? r1 : expm1f(r1);
        outw[i / 2] = pack_h2(r0, r1);
    }
    *(uint4*)(oh + (size_t)node * F + col) =
        make_uint4(outw[0], outw[1], outw[2], outw[3]);
}

// ---------------- split-K HMMA: M32[64,256] += coeff16[64,CW] @ a2[CW,256] ---
// B operand (a2) is row-major [k][c]; transposed in SMEM as half2-interleaved
// sT[c][kk] = {a2[2kk][c], a2[2kk+1][c]}, row stride 36 half2 (conflict-free).
#define PADK2 72
#define STR_T 36
__global__ __launch_bounds__(256) void mgemm_kernel(
    const __half* __restrict__ cf,   // [64][CW]
    const __half* __restrict__ a2,   // [N_PAD][256]
    float* __restrict__ M32)         // [64][256]
{
    __shared__ __align__(16) __half  sA[64 * PADK2];
    __shared__ __align__(8)  __half2 sT[256 * STR_T];

    const int tid  = threadIdx.x;
    const int lane = tid & 31;
    const int wid  = tid >> 5;
    const int wm   = wid & 1;     // 2 warps in M (rows 0-31 / 32-63)
    const int wn   = wid >> 1;    // 4 warps in N (64 cols each)
    const int qr   = lane >> 2;
    const int qc   = (lane & 3) * 2;
    const int k0cta = blockIdx.x * KCH;

    // staging thread map: kk = tid&31 (lane), cg = tid>>5 (warp) -> SMEM stores
    // from a warp hit consecutive 4B addresses (conflict-free).
    const int s_kk = tid & 31;
    const int s_cg = tid >> 5;

    float acc[2][8][4];
    #pragma unroll
    for (int mt = 0; mt < 2; mt++)
        #pragma unroll
        for (int nt = 0; nt < 8; nt++)
            #pragma unroll
            for (int j = 0; j < 4; j++) acc[mt][nt][j] = 0.0f;

    for (int kc = 0; kc < KCH; kc += 64) {
        const int k0 = k0cta + kc;
        // stage sA: coeff16 rows [g][k0..k0+63]: 64 rows x 8 uint4
        #pragma unroll
        for (int t = tid; t < 512; t += 256) {
            int g = t >> 3, i = (t & 7) * 8;
            *(uint4*)&sA[g * PADK2 + i] = *(const uint4*)(cf + (size_t)g * CW + k0 + i);
        }
        // stage sT: transpose a2 chunk [64 x 256] -> sT[c][kk] half2
        {
            int k = k0 + 2 * s_kk;
            uint4 va = make_uint4(0u, 0u, 0u, 0u), vb = va;
            if (k < N_PAD)     va = *(const uint4*)(a2 + (size_t)k * 256 + s_cg * 32 + 0);
            if (k + 1 < N_PAD) vb = *(const uint4*)(a2 + (size_t)(k + 1) * 256 + s_cg * 32 + 0);
            const __half* pa = (const __half*)&va;
            const __half* pb = (const __half*)&vb;
            #pragma unroll
            for (int i = 0; i < 8; i++)
                sT[(s_cg * 32 + i) * STR_T + s_kk] = __halves2half2(pa[i], pb[i]);
            // second 16B group (cols +8..+15), etc: each warp covers 32 cols
            uint4 va2 = make_uint4(0u,0u,0u,0u), vb2 = va2, va3 = va2, vb3 = va2, va4 = va2, vb4 = va2;
            if (k < N_PAD) {
                va2 = *(const uint4*)(a2 + (size_t)k * 256 + s_cg * 32 + 8);
                va3 = *(const uint4*)(a2 + (size_t)k * 256 + s_cg * 32 + 16);
                va4 = *(const uint4*)(a2 + (size_t)k * 256 + s_cg * 32 + 24);
            }
            if (k + 1 < N_PAD) {
                vb2 = *(const uint4*)(a2 + (size_t)(k + 1) * 256 + s_cg * 32 + 8);
                vb3 = *(const uint4*)(a2 + (size_t)(k + 1) * 256 + s_cg * 32 + 16);
                vb4 = *(const uint4*)(a2 + (size_t)(k + 1) * 256 + s_cg * 32 + 24);
            }
            const __half* pa2 = (const __half*)&va2; const __half* pb2 = (const __half*)&vb2;
            const __half* pa3 = (const __half*)&va3; const __half* pb3 = (const __half*)&vb3;
            const __half* pa4 = (const __half*)&va4; const __half* pb4 = (const __half*)&vb4;
            #pragma unroll
            for (int i = 0; i < 8; i++) {
                sT[(s_cg * 32 + 8  + i) * STR_T + s_kk] = __halves2half2(pa2[i], pb2[i]);
                sT[(s_cg * 32 + 16 + i) * STR_T + s_kk] = __halves2half2(pa3[i], pb3[i]);
                sT[(s_cg * 32 + 24 + i) * STR_T + s_kk] = __halves2half2(pa4[i], pb4[i]);
            }
        }
        __syncthreads();

        #pragma unroll
        for (int ks = 0; ks < 4; ks++) {
            const int kb = ks * 16;
            uint32_t ah[2][4];
            #pragma unroll
            for (int mt = 0; mt < 2; mt++) {
                int rr = wm * 32 + mt * 16 + qr;
                ah[mt][0] = *(const uint32_t*)&sA[rr * PADK2 + kb + qc];
                ah[mt][1] = *(const uint32_t*)&sA[(rr + 8) * PADK2 + kb + qc];
                ah[mt][2] = *(const uint32_t*)&sA[rr * PADK2 + kb + qc + 8];
                ah[mt][3] = *(const uint32_t*)&sA[(rr + 8) * PADK2 + kb + qc + 8];
            }
            #pragma unroll
            for (int nt = 0; nt < 8; nt++) {
                int n = wn * 64 + nt * 8 + qr;
                uint32_t b0 = *(const uint32_t*)&sT[n * STR_T + (kb >> 1) + (lane & 3)];
                uint32_t b1 = *(const uint32_t*)&sT[n * STR_T + (kb >> 1) + 4 + (lane & 3)];
                #pragma unroll
                for (int mt = 0; mt < 2; mt++)
                    mma_f16(acc[mt][nt], ah[mt][0], ah[mt][1], ah[mt][2], ah[mt][3],
                            b0, b1);
            }
        }
        __syncthreads();
    }

    // epilogue: scalar red adds into M32
    #pragma unroll
    for (int mt = 0; mt < 2; mt++) {
        #pragma unroll
        for (int nt = 0; nt < 8; nt++) {
            int r0 = wm * 32 + mt * 16 + qr;
            int c0 = wn * 64 + nt * 8 + qc;
            red_add_f32(&M32[r0 * 256 + c0],           acc[mt][nt][0]);
            red_add_f32(&M32[r0 * 256 + c0 + 1],       acc[mt][nt][1]);
            red_add_f32(&M32[(r0 + 8) * 256 + c0],     acc[mt][nt][2]);
            red_add_f32(&M32[(r0 + 8) * 256 + c0 + 1], acc[mt][nt][3]);
        }
    }
}

// ---------------- final: out[g] = M32[g] @ W2 / c_g + b2 ---------------------
__global__ __launch_bounds__(128) void final_out_kernel(
    const float* __restrict__ M32, const float* __restrict__ W2,
    const float* __restrict__ b2, const int* __restrict__ counts,
    float* __restrict__ out)
{
    __shared__ float mrow[HID];
    int g = blockIdx.x;
    int c = threadIdx.x;
    mrow[c] = M32[g * HID + c];
    mrow[c + 128] = M32[g * HID + c + 128];
    __syncthreads();
    float acc = 0.0f;
    #pragma unroll 8
    for (int k = 0; k < HID; k++)
        acc = fmaf(mrow[k], W2[(size_t)k * OUT_CH + c], acc);
    float ic = 1.0f / fmaxf((float)counts[g], 1.0f);
    out[g * OUT_CH + c] = acc * ic + b2[c];
}

__global__ void zero_out_kernel(float* out, int n) {
    int i = blockIdx.x * blockDim.x + threadIdx.x;
    if (i < n) out[i] = 0.0f;
}

// ---------------- launch -----------------------------------------------------
extern "C" void kernel_launch(void* const* d_in, const int* in_sizes, int n_in,
                              void* d_out, int out_size)
{
    const float* x   = nullptr;
    const float* W1  = nullptr;
    const float* b1  = nullptr;
    const float* W2  = nullptr;
    const float* b2  = nullptr;
    const void*  ei  = nullptr;
    const void*  bat = nullptr;

    for (int i = 0; i < n_in; i++) {
        switch (in_sizes[i]) {
            case 12800000: x   = (const float*)d_in[i]; break;
            case 65536:    W1  = (const float*)d_in[i]; break;
            case 256:      b1  = (const float*)d_in[i]; break;
            case 32768:    W2  = (const float*)d_in[i]; break;
            case 128:      b2  = (const float*)d_in[i]; break;
            case 1600000:  ei  = d_in[i];               break;
            case 50000:    bat = d_in[i];               break;
            default: break;
        }
    }
    float* out = (float*)d_out;

    if (!x || !W1 || !b1 || !W2 || !b2 || !ei || !bat) {
        zero_out_kernel<<<(out_size + 255) / 256, 256>>>(out, out_size);
        return;
    }

    void* p;
    cudaGetSymbolAddress(&p, g_dinv);    float* dinv   = (float*)p;
    cudaGetSymbolAddress(&p, g_degi);    int*   degi   = (int*)p;
    cudaGetSymbolAddress(&p, g_offs);    int*   offs   = (int*)p;
    cudaGetSymbolAddress(&p, g_cursor);  int*   cursor = (int*)p;
    cudaGetSymbolAddress(&p, g_partials);int*   parts  = (int*)p;
    cudaGetSymbolAddress(&p, g_ssrc);    int*   ssrc   = (int*)p;
    cudaGetSymbolAddress(&p, g_swgt);    float* swgt   = (float*)p;
    cudaGetSymbolAddress(&p, g_h1);      __half* h1    = (__half*)p;
    cudaGetSymbolAddress(&p, g_counts);  int*   counts = (int*)p;
    cudaGetSymbolAddress(&p, g_src);     int*   src    = (int*)p;
    cudaGetSymbolAddress(&p, g_dst);     int*   dst    = (int*)p;
    cudaGetSymbolAddress(&p, g_batch);   int*   batch  = (int*)p;
    cudaGetSymbolAddress(&p, g_oddcnt);  int*   oddc   = (int*)p;
    cudaGetSymbolAddress(&p, g_a2);      __half* a2    = (__half*)p;
    cudaGetSymbolAddress(&p, g_w1t);     __half* w1t   = (__half*)p;
    cudaGetSymbolAddress(&p, g_coeff32); float* c32    = (float*)p;
    cudaGetSymbolAddress(&p, g_coeff16); __half* c16   = (__half*)p;
    cudaGetSymbolAddress(&p, g_M32);     float* M32    = (float*)p;

    // static host-side resources (streams/events are NOT device memory)
    static cudaStream_t s2 = nullptr;
    static cudaEvent_t evFork = nullptr, evH1 = nullptr, evMid = nullptr, evCoeff = nullptr;
    if (!s2) {
        cudaStreamCreateWithFlags(&s2, cudaStreamNonBlocking);
        cudaEventCreateWithFlags(&evFork, cudaEventDisableTiming);
        cudaEventCreateWithFlags(&evH1, cudaEventDisableTiming);
        cudaEventCreateWithFlags(&evMid, cudaEventDisableTiming);
        cudaEventCreateWithFlags(&evCoeff, cudaEventDisableTiming);
    }

    // ---- fork: weights + GEMM1 on s2 ----
    cudaEventRecord(evFork, 0);
    cudaStreamWaitEvent(s2, evFork, 0);
    conv_w_kernel<<<(HID * IN_CH + 255) / 256, 256, 0, s2>>>(W1, w1t);
    mma_gemm_kernel<<<dim3(HID / 128, N_PAD / 128), 256, 0, s2>>>(x, w1t, h1);
    cudaEventRecord(evH1, s2);

    // ---- main stream: memsets + index prep ----
    cudaMemsetAsync(oddc,   0, 2 * sizeof(int));
    cudaMemsetAsync(degi,   0, N_NODES * sizeof(int));
    cudaMemsetAsync(counts, 0, N_GRAPHS * sizeof(int));
    cudaMemsetAsync(c32,    0, (size_t)N_GRAPHS * CW * sizeof(float));
    cudaMemsetAsync(M32,    0, N_GRAPHS * HID * sizeof(float));

    detect_kernel<<<(825000 + 255) / 256, 256>>>((const int*)ei, (const int*)bat, oddc);
    ei_hist_kernel<<<(N_EDGES + 255) / 256, 256>>>(ei, src, dst, oddc, degi);
    bat_dinv_kernel<<<(N_NODES + 255) / 256, 256>>>(bat, batch, oddc, degi, dinv, counts);
    cudaEventRecord(evMid, 0);

    // ---- s2: coeff matrix build (needs src/dst/batch/dinv) ----
    cudaStreamWaitEvent(s2, evMid, 0);
    coeff_edge_kernel<<<(N_EDGES + 255) / 256, 256, 0, s2>>>(src, dst, batch, dinv, c32);
    coeff_self_kernel<<<(N_NODES + 255) / 256, 256, 0, s2>>>(batch, dinv, c32);
    {
        size_t n = (size_t)N_GRAPHS * CW;
        coeff_conv_kernel<<<(unsigned)((n + 255) / 256), 256, 0, s2>>>(c32, c16);
    }
    cudaEventRecord(evCoeff, s2);

    // ---- main: CSR build ----
    scan1_kernel<<<SCAN_NB, SCAN_BLK>>>(degi, offs, parts);
    scan2_kernel<<<1, 32>>>(parts);
    scan3_kernel<<<(N_NODES + 255) / 256, 256>>>(offs, cursor, parts);
    scatter_build_kernel<<<(N_EDGES + 255) / 256, 256>>>(src, dst, cursor, ssrc, swgt, dinv);

    // ---- join for gather1 (CSR from main, h1 from s2) ----
    cudaStreamWaitEvent(0, evH1, 0);
    gather1_kernel<<<(N_NODES + 3) / 4, 128>>>(offs, degi, ssrc, swgt, dinv, h1, b1, a2);

    // ---- M = coeff16 @ a2 (needs coeff from s2) ----
    cudaStreamWaitEvent(0, evCoeff, 0);
    mgemm_kernel<<<KSPLIT, 256>>>(c16, a2, M32);

    // ---- out = M @ W2 / counts + b2 ----
    final_out_kernel<<<N_GRAPHS, 128>>>(M32, W2, b2, counts, out);
}

// round 16
// speedup vs baseline: 1.3871x; 1.1098x over previous
#include <cuda_runtime.h>
#include <cuda_fp16.h>
#include <cstdint>

#define N_NODES 50000
#define N_PAD   50048      // multiple of 128 for MMA tiles
#define N_EDGES 800000
#define IN_CH 256
#define HID 256
#define OUT_CH 128
#define N_GRAPHS 64
#define SCAN_BLK 512
#define SCAN_NB  ((N_NODES + SCAN_BLK - 1) / SCAN_BLK)   // 98
#define CW    50176        // coeff row width (multiple of 512)
#define KCH   512          // mgemm K per CTA
#define KSPLIT (CW / KCH)  // 98

// ---------------- scratch (device globals; no cudaMalloc allowed) ----------
__device__ float g_dinv[N_NODES];
__device__ int   g_degi[N_NODES];
__device__ int   g_offs[N_NODES];
__device__ int   g_cursor[N_NODES];
__device__ int   g_partials[SCAN_NB];
__device__ int   g_ssrc[N_EDGES];
__device__ float g_swgt[N_EDGES];
__device__ __half g_h1[(size_t)N_PAD * HID];
__device__ int   g_counts[N_GRAPHS];
__device__ int   g_src[N_EDGES];
__device__ int   g_dst[N_EDGES];
__device__ int   g_batch[N_NODES];
// fp16 operands. Pad rows (>= N_NODES / >= used range) stay zero:
// zero-initialized device globals, never written.
__device__ __half g_a2[(size_t)N_PAD * HID];
__device__ __half g_w1t[HID * IN_CH];     // [n][k] = W1[k][n]
__device__ __half g_coeff16[(size_t)N_GRAPHS * CW];
__device__ float  g_M32[N_GRAPHS * HID];  // 64 x 256 fp32

// ---------------- helpers ---------------------------------------------------
__device__ __forceinline__ void red_add_f32(float* addr, float v) {
    asm volatile("red.global.add.f32 [%0], %1;" :: "l"(addr), "f"(v) : "memory");
}
__device__ __forceinline__ void mma_f16(float* c, uint32_t a0, uint32_t a1,
                                        uint32_t a2, uint32_t a3,
                                        uint32_t b0, uint32_t b1) {
    asm volatile("mma.sync.aligned.m16n8k16.row.col.f32.f16.f16.f32 "
                 "{%0,%1,%2,%3}, {%4,%5,%6,%7}, {%8,%9}, {%0,%1,%2,%3};"
                 : "+f"(c[0]), "+f"(c[1]), "+f"(c[2]), "+f"(c[3])
                 : "r"(a0), "r"(a1), "r"(a2), "r"(a3), "r"(b0), "r"(b1));
}
__device__ __forceinline__ uint32_t pack_h2(float a, float b) {
    __half2 h = __floats2half2_rn(a, b);
    return *reinterpret_cast<uint32_t*>(&h);
}

// ---- in-kernel dtype detection: warp scans 128 odd int32 slots at a TAIL
// window of the buffer. int64 (values < 2^31): odd dwords all 0. int32: tail
// values (random ids / batch ~63) are ~all nonzero. Redundant per warp; the
// window is L2-cached after the first access.
__device__ __forceinline__ bool is_int64_tail(const int* __restrict__ buf32, int base) {
    int lane = threadIdx.x & 31;
    int nz = 0;
    #pragma unroll
    for (int i = lane; i < 128; i += 32)
        nz += (buf32[base + 2 * i + 1] != 0);
    #pragma unroll
    for (int d = 16; d; d >>= 1) nz += __shfl_xor_sync(0xFFFFFFFFu, nz, d);
    return nz < 8;
}

// fused: dtype detect + edge conversion + degree histogram
__global__ void ei_hist_kernel(const void* __restrict__ ei, int* __restrict__ src,
                               int* __restrict__ dst, int* __restrict__ degi) {
    bool i64 = is_int64_tail((const int*)ei, 1600000 - 256);
    int e = blockIdx.x * blockDim.x + threadIdx.x;
    if (e >= N_EDGES) return;
    int s, d;
    if (i64) { const long long* p = (const long long*)ei; s = (int)p[e]; d = (int)p[N_EDGES + e]; }
    else     { const int* p = (const int*)ei;             s = p[e];      d = p[N_EDGES + e]; }
    s = min(max(s, 0), N_NODES - 1);
    d = min(max(d, 0), N_NODES - 1);
    src[e] = s;
    dst[e] = d;
    atomicAdd(&degi[d], 1);
}
// fused: dtype detect + batch conversion + dinv + warp-aggregated counts
__global__ void bat_dinv_kernel(const void* __restrict__ bat, int* __restrict__ batch,
                                const int* __restrict__ degi, float* __restrict__ dinv,
                                int* __restrict__ counts) {
    bool i64 = is_int64_tail((const int*)bat, 50000 - 256);
    int i = blockIdx.x * blockDim.x + threadIdx.x;
    int lane = threadIdx.x & 31;
    bool active = (i < N_NODES);
    int g = -1;
    if (active) {
        if (i64) g = (int)((const long long*)bat)[i];
        else     g = ((const int*)bat)[i];
        g = min(max(g, 0), N_GRAPHS - 1);
        batch[i] = g;
        dinv[i] = rsqrtf((float)degi[i] + 1.0f);
    }
    // warp-aggregated counts (batch is sorted; runs are long)
    int prev = __shfl_up_sync(0xFFFFFFFFu, g, 1);
    bool head = (lane == 0) || (prev != g);
    unsigned heads = __ballot_sync(0xFFFFFFFFu, head);
    if (active && head) {
        unsigned above = (lane < 31) ? (heads >> (lane + 1)) : 0u;
        int nxt = above ? (lane + 1 + (__ffs(above) - 1)) : 32;
        int limit = min(32, N_NODES - (i - lane));
        if (nxt > limit) nxt = limit;
        atomicAdd(&counts[g], nxt - lane);
    }
}

// ---------------- weight transpose + fp16 convert (W1 only) ------------------
__global__ void conv_w_kernel(const float* __restrict__ W1, __half* __restrict__ w1t) {
    int i = blockIdx.x * blockDim.x + threadIdx.x;
    if (i < HID * IN_CH) {
        int n = i / IN_CH, k = i % IN_CH;
        w1t[(size_t)n * IN_CH + k] = __float2half_rn(W1[(size_t)k * HID + n]);
    }
}

// ---------------- layer-2 coeff matrix build (direct fp16 atomics) ----------
__global__ void coeff_edge_kernel(const int* __restrict__ src, const int* __restrict__ dst,
                                  const int* __restrict__ batch,
                                  const float* __restrict__ dinv,
                                  __half* __restrict__ c16) {
    int e = blockIdx.x * blockDim.x + threadIdx.x;
    if (e >= N_EDGES) return;
    int s = src[e], d = dst[e];
    atomicAdd(&c16[(size_t)batch[d] * CW + s], __float2half(dinv[s] * dinv[d]));
}
__global__ void coeff_self_kernel(const int* __restrict__ batch,
                                  const float* __restrict__ dinv,
                                  __half* __restrict__ c16) {
    int j = blockIdx.x * blockDim.x + threadIdx.x;
    if (j >= N_NODES) return;
    float dn = dinv[j];
    size_t idx = (size_t)batch[j] * CW + j;     // unique per j: plain RMW
    c16[idx] = __float2half(__half2float(c16[idx]) + dn * dn);
}

// ---------------- CSR scan ----------------------------------------------------
__global__ __launch_bounds__(SCAN_BLK) void scan1_kernel(
    const int* __restrict__ degi, int* __restrict__ offs, int* __restrict__ partials) {
    __shared__ int sm[SCAN_BLK];
    int i = blockIdx.x * SCAN_BLK + threadIdx.x;
    int v = (i < N_NODES) ? degi[i] : 0;
    sm[threadIdx.x] = v;
    __syncthreads();
    for (int d = 1; d < SCAN_BLK; d <<= 1) {
        int t = (threadIdx.x >= d) ? sm[threadIdx.x - d] : 0;
        __syncthreads();
        sm[threadIdx.x] += t;
        __syncthreads();
    }
    if (i < N_NODES) offs[i] = sm[threadIdx.x] - v;       // exclusive
    if (threadIdx.x == SCAN_BLK - 1) partials[blockIdx.x] = sm[SCAN_BLK - 1];
}
// scan3 with inline partials-prefix: warp 0 scans the 98 partials (exclusive)
// into SMEM, then all threads apply. Removes the grid-1 scan2 kernel.
__global__ void scan3_kernel(int* __restrict__ offs, int* __restrict__ cursor,
                             const int* __restrict__ partials) {
    __shared__ int smP[SCAN_NB];
    if (threadIdx.x < 32) {
        int lane = threadIdx.x;
        int run = 0;
        for (int b = 0; b < SCAN_NB; b += 32) {
            int idx = b + lane;
            int orig = (idx < SCAN_NB) ? partials[idx] : 0;
            int v = orig;
            #pragma unroll
            for (int d = 1; d < 32; d <<= 1) {
                int t = __shfl_up_sync(0xFFFFFFFFu, v, d);
                if (lane >= d) v += t;
            }
            if (idx < SCAN_NB) smP[idx] = run + v - orig;   // exclusive
            run += __shfl_sync(0xFFFFFFFFu, v, 31);
        }
    }
    __syncthreads();
    int i = blockIdx.x * blockDim.x + threadIdx.x;
    if (i < N_NODES) {
        int o = offs[i] + smP[i / SCAN_BLK];
        offs[i] = o;
        cursor[i] = o;
    }
}
__global__ void scatter_build_kernel(const int* __restrict__ src, const int* __restrict__ dst,
                                     int* __restrict__ cursor, int* __restrict__ ssrc,
                                     float* __restrict__ swgt,
                                     const float* __restrict__ dinv) {
    int e = blockIdx.x * blockDim.x + threadIdx.x;
    if (e >= N_EDGES) return;
    int s = src[e], d = dst[e];
    int pos = atomicAdd(&cursor[d], 1);
    ssrc[pos] = s;
    swgt[pos] = dinv[s] * dinv[d];
}

// ---------------- HMMA GEMM1: h1[Mpad,256] = x @ W1 (A fp32 -> fp16) --------
#define PADK 40
__global__ __launch_bounds__(256) void mma_gemm_kernel(
    const float* __restrict__ A,
    const __half* __restrict__ B,
    __half* __restrict__ C)
{
    constexpr int NT = HID;
    constexpr int K = 256;
    __shared__ __align__(16) __half sA[128 * PADK];
    __shared__ __align__(16) __half sB[128 * PADK];

    const int tid  = threadIdx.x;
    const int lane = tid & 31;
    const int wid  = tid >> 5;
    const int wm   = wid & 3;
    const int wn   = wid >> 2;
    const int bm   = blockIdx.y * 128;
    const int bn   = blockIdx.x * 128;

    const int r0l = tid >> 2, i0l = (tid & 3) * 8;
    const int r1l = r0l + 64;

    float acc[2][8][4];
    #pragma unroll
    for (int mt = 0; mt < 2; mt++)
        #pragma unroll
        for (int nt = 0; nt < 8; nt++)
            #pragma unroll
            for (int j = 0; j < 4; j++) acc[mt][nt][j] = 0.0f;

    const int qr = lane >> 2;
    const int qc = (lane & 3) * 2;

    float4 pAf[2][2];
    uint4  pB[2];

    auto prefetch = [&](int kc) {
        #pragma unroll
        for (int it = 0; it < 2; it++) {
            int r = (it == 0) ? r0l : r1l;
            if (bm + r < N_NODES) {
                size_t gi = (size_t)(bm + r) * K + kc + i0l;
                pAf[it][0] = *(const float4*)(A + gi);
                pAf[it][1] = *(const float4*)(A + gi + 4);
            } else {
                pAf[it][0] = make_float4(0.f, 0.f, 0.f, 0.f);
                pAf[it][1] = make_float4(0.f, 0.f, 0.f, 0.f);
            }
        }
        #pragma unroll
        for (int it = 0; it < 2; it++) {
            int r = (it == 0) ? r0l : r1l;
            size_t gi = (size_t)(bn + r) * K + kc + i0l;
            pB[it] = *(const uint4*)(B + gi);
        }
    };

    auto stage = [&]() {
        #pragma unroll
        for (int it = 0; it < 2; it++) {
            int r = (it == 0) ? r0l : r1l;
            uint4 v;
            v.x = pack_h2(pAf[it][0].x, pAf[it][0].y);
            v.y = pack_h2(pAf[it][0].z, pAf[it][0].w);
            v.z = pack_h2(pAf[it][1].x, pAf[it][1].y);
            v.w = pack_h2(pAf[it][1].z, pAf[it][1].w);
            *(uint4*)&sA[r * PADK + i0l] = v;
        }
        #pragma unroll
        for (int it = 0; it < 2; it++) {
            int r = (it == 0) ? r0l : r1l;
            *(uint4*)&sB[r * PADK + i0l] = pB[it];
        }
    };

    prefetch(0);
    for (int kc = 0; kc < K; kc += 32) {
        stage();
        __syncthreads();
        if (kc + 32 < K) prefetch(kc + 32);

        #pragma unroll
        for (int ks = 0; ks < 2; ks++) {
            const int kb = ks * 16;
            uint32_t ah[2][4];
            #pragma unroll
            for (int mt = 0; mt < 2; mt++) {
                int rr = wm * 32 + mt * 16 + qr;
                #pragma unroll
                for (int h = 0; h < 2; h++) {
                    int r = rr + h * 8;
                    ah[mt][h]     = *(const uint32_t*)&sA[r * PADK + kb + qc];
                    ah[mt][h + 2] = *(const uint32_t*)&sA[r * PADK + kb + qc + 8];
                }
            }
            #pragma unroll
            for (int nt = 0; nt < 8; nt++) {
                int n = wn * 64 + nt * 8 + qr;
                uint32_t b0 = *(const uint32_t*)&sB[n * PADK + kb + qc];
                uint32_t b1 = *(const uint32_t*)&sB[n * PADK + kb + qc + 8];
                #pragma unroll
                for (int mt = 0; mt < 2; mt++)
                    mma_f16(acc[mt][nt], ah[mt][0], ah[mt][1], ah[mt][2], ah[mt][3],
                            b0, b1);
            }
        }
        __syncthreads();
    }

    #pragma unroll
    for (int mt = 0; mt < 2; mt++) {
        #pragma unroll
        for (int nt = 0; nt < 8; nt++) {
            int r0 = bm + wm * 32 + mt * 16 + qr;
            int c0 = bn + wn * 64 + nt * 8 + qc;
            *(uint32_t*)(C + (size_t)r0 * NT + c0) = pack_h2(acc[mt][nt][0], acc[mt][nt][1]);
            *(uint32_t*)(C + (size_t)(r0 + 8) * NT + c0) = pack_h2(acc[mt][nt][2], acc[mt][nt][3]);
        }
    }
}

// ---------------- CSR gather layer 1 (fp16 h1 -> fp16 a2) --------------------
__global__ __launch_bounds__(128) void gather1_kernel(
    const int* __restrict__ offs, const int* __restrict__ degi,
    const int* __restrict__ ssrc, const float* __restrict__ swgt,
    const float* __restrict__ dinv,
    const __half* __restrict__ h, const float* __restrict__ bias,
    __half* __restrict__ oh)
{
    constexpr int F = HID;
    int node = blockIdx.x * 4 + (threadIdx.x >> 5);
    int lane = threadIdx.x & 31;
    if (node >= N_NODES) return;

    int start = offs[node];
    int dg    = degi[node];
    float dn  = dinv[node];

    float acc[8];
    #pragma unroll
    for (int v = 0; v < 8; v++) acc[v] = 0.0f;

    auto accum = [&](int s, float w) {
        uint4 v = __ldg((const uint4*)(h + (size_t)s * F) + lane);
        const __half2* hp = (const __half2*)&v;
        #pragma unroll
        for (int i = 0; i < 4; i++) {
            float2 f = __half22float2(hp[i]);
            acc[2 * i]     += w * f.x;
            acc[2 * i + 1] += w * f.y;
        }
    };

    for (int base = 0; base < dg; base += 32) {
        int nch = min(32, dg - base);
        int   s_l = 0;
        float w_l = 0.0f;
        if (lane < nch) {
            s_l = __ldg(&ssrc[start + base + lane]);
            w_l = __ldg(&swgt[start + base + lane]);
        }
        #pragma unroll 4
        for (int j = 0; j < nch; j++) {
            int   s = __shfl_sync(0xFFFFFFFFu, s_l, j);
            float w = __shfl_sync(0xFFFFFFFFu, w_l, j);
            accum(s, w);
        }
    }

    float sl = dn * dn;
    int col = lane * 8;
    float selfv[8];
    {
        uint4 v = __ldg((const uint4*)(h + (size_t)node * F) + lane);
        const __half2* hp = (const __half2*)&v;
        #pragma unroll
        for (int i = 0; i < 4; i++) {
            float2 f = __half22float2(hp[i]);
            selfv[2 * i] = f.x; selfv[2 * i + 1] = f.y;
        }
    }

    uint32_t outw[4];
    #pragma unroll
    for (int i = 0; i < 8; i += 2) {
        float r0 = acc[i]     + selfv[i]     * sl + bias[col + i];
        float r1 = acc[i + 1] + selfv[i + 1] * sl + bias[col + i + 1];
        r0 = r0 > 0.f ? r0 : expm1f(r0);
        r1 = r1 > 0.f ? r1 : expm1f(r1);
        outw[i / 2] = pack_h2(r0, r1);
    }
    *(uint4*)(oh + (size_t)node * F + col) =
        make_uint4(outw[0], outw[1], outw[2], outw[3]);
}

// ---------------- split-K HMMA: M32[64,256] += coeff16[64,CW] @ a2[CW,256] ---
#define PADK2 72
#define STR_T 36
__global__ __launch_bounds__(256) void mgemm_kernel(
    const __half* __restrict__ cf,   // [64][CW]
    const __half* __restrict__ a2,   // [N_PAD][256]
    float* __restrict__ M32)         // [64][256]
{
    __shared__ __align__(16) __half  sA[64 * PADK2];
    __shared__ __align__(8)  __half2 sT[256 * STR_T];

    const int tid  = threadIdx.x;
    const int lane = tid & 31;
    const int wid  = tid >> 5;
    const int wm   = wid & 1;
    const int wn   = wid >> 1;
    const int qr   = lane >> 2;
    const int qc   = (lane & 3) * 2;
    const int k0cta = blockIdx.x * KCH;

    const int s_kk = tid & 31;
    const int s_cg = tid >> 5;

    float acc[2][8][4];
    #pragma unroll
    for (int mt = 0; mt < 2; mt++)
        #pragma unroll
        for (int nt = 0; nt < 8; nt++)
            #pragma unroll
            for (int j = 0; j < 4; j++) acc[mt][nt][j] = 0.0f;

    for (int kc = 0; kc < KCH; kc += 64) {
        const int k0 = k0cta + kc;
        #pragma unroll
        for (int t = tid; t < 512; t += 256) {
            int g = t >> 3, i = (t & 7) * 8;
            *(uint4*)&sA[g * PADK2 + i] = *(const uint4*)(cf + (size_t)g * CW + k0 + i);
        }
        {
            int k = k0 + 2 * s_kk;
            uint4 va = make_uint4(0u, 0u, 0u, 0u), vb = va;
            if (k < N_PAD)     va = *(const uint4*)(a2 + (size_t)k * 256 + s_cg * 32 + 0);
            if (k + 1 < N_PAD) vb = *(const uint4*)(a2 + (size_t)(k + 1) * 256 + s_cg * 32 + 0);
            const __half* pa = (const __half*)&va;
            const __half* pb = (const __half*)&vb;
            #pragma unroll
            for (int i = 0; i < 8; i++)
                sT[(s_cg * 32 + i) * STR_T + s_kk] = __halves2half2(pa[i], pb[i]);
            uint4 va2 = make_uint4(0u,0u,0u,0u), vb2 = va2, va3 = va2, vb3 = va2, va4 = va2, vb4 = va2;
            if (k < N_PAD) {
                va2 = *(const uint4*)(a2 + (size_t)k * 256 + s_cg * 32 + 8);
                va3 = *(const uint4*)(a2 + (size_t)k * 256 + s_cg * 32 + 16);
                va4 = *(const uint4*)(a2 + (size_t)k * 256 + s_cg * 32 + 24);
            }
            if (k + 1 < N_PAD) {
                vb2 = *(const uint4*)(a2 + (size_t)(k + 1) * 256 + s_cg * 32 + 8);
                vb3 = *(const uint4*)(a2 + (size_t)(k + 1) * 256 + s_cg * 32 + 16);
                vb4 = *(const uint4*)(a2 + (size_t)(k + 1) * 256 + s_cg * 32 + 24);
            }
            const __half* pa2 = (const __half*)&va2; const __half* pb2 = (const __half*)&vb2;
            const __half* pa3 = (const __half*)&va3; const __half* pb3 = (const __half*)&vb3;
            const __half* pa4 = (const __half*)&va4; const __half* pb4 = (const __half*)&vb4;
            #pragma unroll
            for (int i = 0; i < 8; i++) {
                sT[(s_cg * 32 + 8  + i) * STR_T + s_kk] = __halves2half2(pa2[i], pb2[i]);
                sT[(s_cg * 32 + 16 + i) * STR_T + s_kk] = __halves2half2(pa3[i], pb3[i]);
                sT[(s_cg * 32 + 24 + i) * STR_T + s_kk] = __halves2half2(pa4[i], pb4[i]);
            }
        }
        __syncthreads();

        #pragma unroll
        for (int ks = 0; ks < 4; ks++) {
            const int kb = ks * 16;
            uint32_t ah[2][4];
            #pragma unroll
            for (int mt = 0; mt < 2; mt++) {
                int rr = wm * 32 + mt * 16 + qr;
                ah[mt][0] = *(const uint32_t*)&sA[rr * PADK2 + kb + qc];
                ah[mt][1] = *(const uint32_t*)&sA[(rr + 8) * PADK2 + kb + qc];
                ah[mt][2] = *(const uint32_t*)&sA[rr * PADK2 + kb + qc + 8];
                ah[mt][3] = *(const uint32_t*)&sA[(rr + 8) * PADK2 + kb + qc + 8];
            }
            #pragma unroll
            for (int nt = 0; nt < 8; nt++) {
                int n = wn * 64 + nt * 8 + qr;
                uint32_t b0 = *(const uint32_t*)&sT[n * STR_T + (kb >> 1) + (lane & 3)];
                uint32_t b1 = *(const uint32_t*)&sT[n * STR_T + (kb >> 1) + 4 + (lane & 3)];
                #pragma unroll
                for (int mt = 0; mt < 2; mt++)
                    mma_f16(acc[mt][nt], ah[mt][0], ah[mt][1], ah[mt][2], ah[mt][3],
                            b0, b1);
            }
        }
        __syncthreads();
    }

    #pragma unroll
    for (int mt = 0; mt < 2; mt++) {
        #pragma unroll
        for (int nt = 0; nt < 8; nt++) {
            int r0 = wm * 32 + mt * 16 + qr;
            int c0 = wn * 64 + nt * 8 + qc;
            red_add_f32(&M32[r0 * 256 + c0],           acc[mt][nt][0]);
            red_add_f32(&M32[r0 * 256 + c0 + 1],       acc[mt][nt][1]);
            red_add_f32(&M32[(r0 + 8) * 256 + c0],     acc[mt][nt][2]);
            red_add_f32(&M32[(r0 + 8) * 256 + c0 + 1], acc[mt][nt][3]);
        }
    }
}

// ---------------- final: out[g] = M32[g] @ W2 / c_g + b2 ---------------------
__global__ __launch_bounds__(128) void final_out_kernel(
    const float* __restrict__ M32, const float* __restrict__ W2,
    const float* __restrict__ b2, const int* __restrict__ counts,
    float* __restrict__ out)
{
    __shared__ float mrow[HID];
    int g = blockIdx.x;
    int c = threadIdx.x;
    mrow[c] = M32[g * HID + c];
    mrow[c + 128] = M32[g * HID + c + 128];
    __syncthreads();
    float acc = 0.0f;
    #pragma unroll 8
    for (int k = 0; k < HID; k++)
        acc = fmaf(mrow[k], W2[(size_t)k * OUT_CH + c], acc);
    float ic = 1.0f / fmaxf((float)counts[g], 1.0f);
    out[g * OUT_CH + c] = acc * ic + b2[c];
}

__global__ void zero_out_kernel(float* out, int n) {
    int i = blockIdx.x * blockDim.x + threadIdx.x;
    if (i < n) out[i] = 0.0f;
}

// ---------------- launch -----------------------------------------------------
extern "C" void kernel_launch(void* const* d_in, const int* in_sizes, int n_in,
                              void* d_out, int out_size)
{
    const float* x   = nullptr;
    const float* W1  = nullptr;
    const float* b1  = nullptr;
    const float* W2  = nullptr;
    const float* b2  = nullptr;
    const void*  ei  = nullptr;
    const void*  bat = nullptr;

    for (int i = 0; i < n_in; i++) {
        switch (in_sizes[i]) {
            case 12800000: x   = (const float*)d_in[i]; break;
            case 65536:    W1  = (const float*)d_in[i]; break;
            case 256:      b1  = (const float*)d_in[i]; break;
            case 32768:    W2  = (const float*)d_in[i]; break;
            case 128:      b2  = (const float*)d_in[i]; break;
            case 1600000:  ei  = d_in[i];               break;
            case 50000:    bat = d_in[i];               break;
            default: break;
        }
    }
    float* out = (float*)d_out;

    if (!x || !W1 || !b1 || !W2 || !b2 || !ei || !bat) {
        zero_out_kernel<<<(out_size + 255) / 256, 256>>>(out, out_size);
        return;
    }

    void* p;
    cudaGetSymbolAddress(&p, g_dinv);    float* dinv   = (float*)p;
    cudaGetSymbolAddress(&p, g_degi);    int*   degi   = (int*)p;
    cudaGetSymbolAddress(&p, g_offs);    int*   offs   = (int*)p;
    cudaGetSymbolAddress(&p, g_cursor);  int*   cursor = (int*)p;
    cudaGetSymbolAddress(&p, g_partials);int*   parts  = (int*)p;
    cudaGetSymbolAddress(&p, g_ssrc);    int*   ssrc   = (int*)p;
    cudaGetSymbolAddress(&p, g_swgt);    float* swgt   = (float*)p;
    cudaGetSymbolAddress(&p, g_h1);      __half* h1    = (__half*)p;
    cudaGetSymbolAddress(&p, g_counts);  int*   counts = (int*)p;
    cudaGetSymbolAddress(&p, g_src);     int*   src    = (int*)p;
    cudaGetSymbolAddress(&p, g_dst);     int*   dst    = (int*)p;
    cudaGetSymbolAddress(&p, g_batch);   int*   batch  = (int*)p;
    cudaGetSymbolAddress(&p, g_a2);      __half* a2    = (__half*)p;
    cudaGetSymbolAddress(&p, g_w1t);     __half* w1t   = (__half*)p;
    cudaGetSymbolAddress(&p, g_coeff16); __half* c16   = (__half*)p;
    cudaGetSymbolAddress(&p, g_M32);     float* M32    = (float*)p;

    // static host-side resources (streams/events are NOT device memory)
    static cudaStream_t s2 = nullptr;
    static cudaEvent_t evFork = nullptr, evH1 = nullptr, evMid = nullptr, evCoeff = nullptr;
    if (!s2) {
        cudaStreamCreateWithFlags(&s2, cudaStreamNonBlocking);
        cudaEventCreateWithFlags(&evFork, cudaEventDisableTiming);
        cudaEventCreateWithFlags(&evH1, cudaEventDisableTiming);
        cudaEventCreateWithFlags(&evMid, cudaEventDisableTiming);
        cudaEventCreateWithFlags(&evCoeff, cudaEventDisableTiming);
    }

    // ---- fork: weights + GEMM1 on s2 ----
    cudaEventRecord(evFork, 0);
    cudaStreamWaitEvent(s2, evFork, 0);
    conv_w_kernel<<<(HID * IN_CH + 255) / 256, 256, 0, s2>>>(W1, w1t);
    mma_gemm_kernel<<<dim3(HID / 128, N_PAD / 128), 256, 0, s2>>>(x, w1t, h1);
    cudaEventRecord(evH1, s2);
    // coeff buffers zeroed on s2 (off the main chain)
    cudaMemsetAsync(c16, 0, (size_t)N_GRAPHS * CW * sizeof(__half), s2);
    cudaMemsetAsync(M32, 0, N_GRAPHS * HID * sizeof(float), s2);

    // ---- main stream: index prep ----
    cudaMemsetAsync(degi,   0, N_NODES * sizeof(int));
    cudaMemsetAsync(counts, 0, N_GRAPHS * sizeof(int));

    ei_hist_kernel<<<(N_EDGES + 255) / 256, 256>>>(ei, src, dst, degi);
    bat_dinv_kernel<<<(N_NODES + 255) / 256, 256>>>(bat, batch, degi, dinv, counts);
    cudaEventRecord(evMid, 0);

    // ---- s2: coeff matrix build (needs src/dst/batch/dinv) ----
    cudaStreamWaitEvent(s2, evMid, 0);
    coeff_edge_kernel<<<(N_EDGES + 255) / 256, 256, 0, s2>>>(src, dst, batch, dinv, c16);
    coeff_self_kernel<<<(N_NODES + 255) / 256, 256, 0, s2>>>(batch, dinv, c16);
    cudaEventRecord(evCoeff, s2);

    // ---- main: CSR build ----
    scan1_kernel<<<SCAN_NB, SCAN_BLK>>>(degi, offs, parts);
    scan3_kernel<<<(N_NODES + 255) / 256, 256>>>(offs, cursor, parts);
    scatter_build_kernel<<<(N_EDGES + 255) / 256, 256>>>(src, dst, cursor, ssrc, swgt, dinv);

    // ---- join for gather1 (CSR from main, h1 from s2) ----
    cudaStreamWaitEvent(0, evH1, 0);
    gather1_kernel<<<(N_NODES + 3) / 4, 128>>>(offs, degi, ssrc, swgt, dinv, h1, b1, a2);

    // ---- M = coeff16 @ a2 (needs coeff from s2) ----
    cudaStreamWaitEvent(0, evCoeff, 0);
    mgemm_kernel<<<KSPLIT, 256>>>(c16, a2, M32);

    // ---- out = M @ W2 / counts + b2 ----
    final_out_kernel<<<N_GRAPHS, 128>>>(M32, W2, b2, counts, out);
}